// round 1
// baseline (speedup 1.0000x reference)
#include <cuda_runtime.h>
#include <math.h>

// Problem dims (compile-time)
#define HID   1024
#define SEQ   2048
#define BATCH 4
#define NH    16
#define NG    1024
#define M_TOT (BATCH * SEQ)   // 8192
#define SCALE 0.125f          // 1/sqrt(64)

// Scratch: linear [B,S,HID] fp32 buffers (static device arrays — no allocs)
__device__ float g_q[(size_t)M_TOT * HID];
__device__ float g_k[(size_t)M_TOT * HID];
__device__ float g_v[(size_t)M_TOT * HID];
__device__ float g_ctx[(size_t)M_TOT * HID];

// ---------------------------------------------------------------------------
// SGEMM (NT): C[m,n] = sum_k A[m,k] * W[n,k] + bias[n]
// A: [M_TOT, 1024], W: [1024, 1024], both K-contiguous. 128x128 block tile,
// K-chunk 8, 256 threads, 8x8 per thread in 4 4x4 sub-tiles (conflict-free LDS).
// ---------------------------------------------------------------------------
__global__ __launch_bounds__(256) void sgemm_nt_bias(
    const float* __restrict__ A, const float* __restrict__ W,
    const float* __restrict__ bias, float* __restrict__ C)
{
    __shared__ float As[8][128];
    __shared__ float Bs[8][128];

    const int tid  = threadIdx.x;
    const int bm   = blockIdx.y;
    const int bn   = blockIdx.x;
    const float* Ab = A + (size_t)bm * 128 * HID;
    const float* Wb = W + (size_t)bn * 128 * HID;

    const int lrow = tid >> 1;          // 0..127
    const int lk   = (tid & 1) * 4;     // 0 or 4
    const int tx   = tid & 15;
    const int ty   = tid >> 4;

    float acc[8][8];
#pragma unroll
    for (int i = 0; i < 8; i++)
#pragma unroll
        for (int j = 0; j < 8; j++) acc[i][j] = 0.0f;

    for (int k0 = 0; k0 < HID; k0 += 8) {
        float4 av = *(const float4*)(Ab + (size_t)lrow * HID + k0 + lk);
        float4 bv = *(const float4*)(Wb + (size_t)lrow * HID + k0 + lk);
        __syncthreads();
        As[lk + 0][lrow] = av.x; As[lk + 1][lrow] = av.y;
        As[lk + 2][lrow] = av.z; As[lk + 3][lrow] = av.w;
        Bs[lk + 0][lrow] = bv.x; Bs[lk + 1][lrow] = bv.y;
        Bs[lk + 2][lrow] = bv.z; Bs[lk + 3][lrow] = bv.w;
        __syncthreads();
#pragma unroll
        for (int kk = 0; kk < 8; kk++) {
            float a[8], b[8];
            *(float4*)&a[0] = *(const float4*)&As[kk][ty * 4];
            *(float4*)&a[4] = *(const float4*)&As[kk][64 + ty * 4];
            *(float4*)&b[0] = *(const float4*)&Bs[kk][tx * 4];
            *(float4*)&b[4] = *(const float4*)&Bs[kk][64 + tx * 4];
#pragma unroll
            for (int i = 0; i < 8; i++)
#pragma unroll
                for (int j = 0; j < 8; j++) acc[i][j] += a[i] * b[j];
        }
    }

#pragma unroll
    for (int i = 0; i < 8; i++) {
        const int row = bm * 128 + ((i < 4) ? (ty * 4 + i) : (64 + ty * 4 + i - 4));
#pragma unroll
        for (int jh = 0; jh < 2; jh++) {
            const int col = bn * 128 + jh * 64 + tx * 4;
            const float4 bb = *(const float4*)(bias + col);
            float4 r;
            r.x = acc[i][jh * 4 + 0] + bb.x;
            r.y = acc[i][jh * 4 + 1] + bb.y;
            r.z = acc[i][jh * 4 + 2] + bb.z;
            r.w = acc[i][jh * 4 + 3] + bb.w;
            *(float4*)(C + (size_t)row * HID + col) = r;
        }
    }
}

// ---------------------------------------------------------------------------
// Flash attention over groups. Block = one (b, h, 64-group q-tile).
// Group (g,d) <-> qlin row 2g + d/64, col h*64 + d%64.
// Q,K stored d-major (transposed) in smem for conflict-free score GEMM;
// V stored in natural seq-row layout for the P@V stage.
// Output ctx written to g_ctx linear layout: row 2g + h/8, col (h%8)*128 + d.
// ---------------------------------------------------------------------------
#define P68 68   // smem pitch (16B-aligned, decent bank spread)

__global__ __launch_bounds__(256) void attn_kernel(
    const float* __restrict__ qlin, const float* __restrict__ klin,
    const float* __restrict__ vlin, float* __restrict__ ctx)
{
    extern __shared__ float sm[];
    float* Qt = sm;                    // [128 d][64 i]  pitch P68
    float* Kt = Qt + 128 * P68;        // [128 d][64 j]
    float* Vs = Kt + 128 * P68;        // [128 row][64 col]
    float* Ps = Vs + 128 * P68;        // [64 i][64 j]
    float* row_m = Ps + 64 * P68;      // [64]
    float* row_l = row_m + 64;         // [64]
    float* row_a = row_l + 64;         // [64]

    const int tid = threadIdx.x;
    const int gt  = blockIdx.x;        // 0..15 q-tile
    const int h   = blockIdx.y;        // 0..15
    const int b   = blockIdx.z;        // 0..3
    const int g0  = gt * 64;
    const size_t bbase = (size_t)b * SEQ * HID;
    const float* qb = qlin + bbase;
    const float* kb = klin + bbase;
    const float* vb = vlin + bbase;
    const int hcol = h * 64;

    const int tx = tid & 15;           // S stage: j-block; PV stage: d-block
    const int ty = tid >> 4;           // i-block

    // --- load Q tile transposed: Qt[d][i] ---
    for (int idx = tid; idx < 64 * 32; idx += 256) {
        const int i  = idx >> 5;
        const int d  = (idx & 31) * 4;
        const int par = d >> 6;
        const int c   = d & 63;
        float4 v = *(const float4*)(qb + (size_t)(2 * (g0 + i) + par) * HID + hcol + c);
        Qt[(d + 0) * P68 + i] = v.x;
        Qt[(d + 1) * P68 + i] = v.y;
        Qt[(d + 2) * P68 + i] = v.z;
        Qt[(d + 3) * P68 + i] = v.w;
    }
    if (tid < 64) { row_m[tid] = -1e30f; row_l[tid] = 0.0f; }

    float o[4][8];
#pragma unroll
    for (int r = 0; r < 4; r++)
#pragma unroll
        for (int c = 0; c < 8; c++) o[r][c] = 0.0f;

    __syncthreads();

    for (int j0 = 0; j0 < NG; j0 += 64) {
        // --- load K chunk transposed, V chunk natural ---
        for (int idx = tid; idx < 64 * 32; idx += 256) {
            const int j  = idx >> 5;
            const int d  = (idx & 31) * 4;
            const int par = d >> 6;
            const int c   = d & 63;
            float4 v = *(const float4*)(kb + (size_t)(2 * (j0 + j) + par) * HID + hcol + c);
            Kt[(d + 0) * P68 + j] = v.x;
            Kt[(d + 1) * P68 + j] = v.y;
            Kt[(d + 2) * P68 + j] = v.z;
            Kt[(d + 3) * P68 + j] = v.w;
        }
        for (int idx = tid; idx < 128 * 16; idx += 256) {
            const int r  = idx >> 4;
            const int c4 = (idx & 15) * 4;
            float4 v = *(const float4*)(vb + (size_t)(2 * j0 + r) * HID + hcol + c4);
            *(float4*)&Vs[r * P68 + c4] = v;
        }
        __syncthreads();

        // --- scores S[i,j] = sum_d Q[i,d] K[j,d], i=ty*4+., j=tx*4+. ---
        float sacc[4][4];
#pragma unroll
        for (int r = 0; r < 4; r++)
#pragma unroll
            for (int j = 0; j < 4; j++) sacc[r][j] = 0.0f;

#pragma unroll 4
        for (int d = 0; d < 128; d++) {
            float4 qa = *(const float4*)&Qt[d * P68 + ty * 4];
            float4 kk = *(const float4*)&Kt[d * P68 + tx * 4];
            const float qv[4] = {qa.x, qa.y, qa.z, qa.w};
            const float kv[4] = {kk.x, kk.y, kk.z, kk.w};
#pragma unroll
            for (int r = 0; r < 4; r++)
#pragma unroll
                for (int j = 0; j < 4; j++) sacc[r][j] += qv[r] * kv[j];
        }
#pragma unroll
        for (int r = 0; r < 4; r++)
#pragma unroll
            for (int j = 0; j < 4; j++)
                Ps[(ty * 4 + r) * P68 + tx * 4 + j] = sacc[r][j] * SCALE;
        __syncthreads();

        // --- online softmax, one thread per row ---
        if (tid < 64) {
            const int i = tid;
            float mc = -1e30f;
#pragma unroll 8
            for (int j = 0; j < 64; j++) mc = fmaxf(mc, Ps[i * P68 + j]);
            const float m_old = row_m[i];
            const float m_new = fmaxf(m_old, mc);
            const float alpha = __expf(m_old - m_new);
            float l = row_l[i] * alpha;
#pragma unroll 8
            for (int j = 0; j < 64; j++) {
                const float p = __expf(Ps[i * P68 + j] - m_new);
                Ps[i * P68 + j] = p;
                l += p;
            }
            row_m[i] = m_new;
            row_l[i] = l;
            row_a[i] = alpha;
        }
        __syncthreads();

        // --- rescale O, accumulate P @ V. thread: rows ty*4+r, cols tx*8+dd ---
        {
            float al[4];
#pragma unroll
            for (int r = 0; r < 4; r++) al[r] = row_a[ty * 4 + r];
#pragma unroll
            for (int r = 0; r < 4; r++)
#pragma unroll
                for (int c = 0; c < 8; c++) o[r][c] *= al[r];

            const int vr_par = (tx >> 3);          // d >= 64 ?
            const int vcol   = (tx & 7) * 8;
#pragma unroll 2
            for (int j = 0; j < 64; j++) {
                const float* vp = &Vs[(2 * j + vr_par) * P68 + vcol];
                float4 v0 = *(const float4*)vp;
                float4 v1 = *(const float4*)(vp + 4);
                float p[4];
#pragma unroll
                for (int r = 0; r < 4; r++) p[r] = Ps[(ty * 4 + r) * P68 + j];
#pragma unroll
                for (int r = 0; r < 4; r++) {
                    o[r][0] += p[r] * v0.x; o[r][1] += p[r] * v0.y;
                    o[r][2] += p[r] * v0.z; o[r][3] += p[r] * v0.w;
                    o[r][4] += p[r] * v1.x; o[r][5] += p[r] * v1.y;
                    o[r][6] += p[r] * v1.z; o[r][7] += p[r] * v1.w;
                }
            }
        }
        __syncthreads();   // protect Kt/Vs/Ps for next chunk
    }

    // --- epilogue: normalize & scatter to linear ctx layout ---
    float* cb = ctx + bbase;
#pragma unroll
    for (int r = 0; r < 4; r++) {
        const int i = ty * 4 + r;
        const float inv = 1.0f / row_l[i];
        const int g = g0 + i;
        const int orow = 2 * g + (h >> 3);
        const int ocol = (h & 7) * 128 + tx * 8;
        float4 w0, w1;
        w0.x = o[r][0] * inv; w0.y = o[r][1] * inv;
        w0.z = o[r][2] * inv; w0.w = o[r][3] * inv;
        w1.x = o[r][4] * inv; w1.y = o[r][5] * inv;
        w1.z = o[r][6] * inv; w1.w = o[r][7] * inv;
        *(float4*)(cb + (size_t)orow * HID + ocol)     = w0;
        *(float4*)(cb + (size_t)orow * HID + ocol + 4) = w1;
    }
}

// ---------------------------------------------------------------------------
extern "C" void kernel_launch(void* const* d_in, const int* in_sizes, int n_in,
                              void* d_out, int out_size)
{
    const float* x  = (const float*)d_in[0];
    const float* Wq = (const float*)d_in[1];
    const float* bq = (const float*)d_in[2];
    const float* Wk = (const float*)d_in[3];
    const float* bk = (const float*)d_in[4];
    const float* Wv = (const float*)d_in[5];
    const float* bv = (const float*)d_in[6];
    const float* Wo = (const float*)d_in[7];
    const float* bo = (const float*)d_in[8];
    float* out = (float*)d_out;

    float *q, *k, *v, *ctx;
    cudaGetSymbolAddress((void**)&q,   g_q);
    cudaGetSymbolAddress((void**)&k,   g_k);
    cudaGetSymbolAddress((void**)&v,   g_v);
    cudaGetSymbolAddress((void**)&ctx, g_ctx);

    const dim3 gemm_grid(HID / 128, M_TOT / 128);   // (8, 64)
    sgemm_nt_bias<<<gemm_grid, 256>>>(x, Wq, bq, q);
    sgemm_nt_bias<<<gemm_grid, 256>>>(x, Wk, bk, k);
    sgemm_nt_bias<<<gemm_grid, 256>>>(x, Wv, bv, v);

    const int smem_bytes = (3 * 128 * P68 + 64 * P68 + 3 * 64) * (int)sizeof(float);
    cudaFuncSetAttribute(attn_kernel,
                         cudaFuncAttributeMaxDynamicSharedMemorySize, smem_bytes);
    attn_kernel<<<dim3(NG / 64, NH, BATCH), 256, smem_bytes>>>(q, k, v, ctx);

    sgemm_nt_bias<<<gemm_grid, 256>>>(ctx, Wo, bo, out);
}

// round 2
// speedup vs baseline: 1.0024x; 1.0024x over previous
#include <cuda_runtime.h>
#include <math.h>

// Problem dims (compile-time)
#define HID   1024
#define SEQ   2048
#define BATCH 4
#define NH    16
#define NG    1024
#define M_TOT (BATCH * SEQ)   // 8192
#define SCALE 0.125f          // 1/sqrt(64)

// Scratch: linear [B,S,HID] fp32 buffers (static device arrays — no allocs)
__device__ float g_q[(size_t)M_TOT * HID];
__device__ float g_k[(size_t)M_TOT * HID];
__device__ float g_v[(size_t)M_TOT * HID];
__device__ float g_ctx[(size_t)M_TOT * HID];

// ---------------------------------------------------------------------------
// SGEMM (NT): C[m,n] = sum_k A[m,k] * W[n,k] + bias[n]
// A: [M_TOT, 1024], W: [1024, 1024], both K-contiguous. 128x128 block tile,
// K-chunk 8, 256 threads, 8x8 per thread in 4 4x4 sub-tiles (conflict-free LDS).
// ---------------------------------------------------------------------------
__global__ __launch_bounds__(256) void sgemm_nt_bias(
    const float* __restrict__ A, const float* __restrict__ W,
    const float* __restrict__ bias, float* __restrict__ C)
{
    __shared__ float As[8][128];
    __shared__ float Bs[8][128];

    const int tid  = threadIdx.x;
    const int bm   = blockIdx.y;
    const int bn   = blockIdx.x;
    const float* Ab = A + (size_t)bm * 128 * HID;
    const float* Wb = W + (size_t)bn * 128 * HID;

    const int lrow = tid >> 1;          // 0..127
    const int lk   = (tid & 1) * 4;     // 0 or 4
    const int tx   = tid & 15;
    const int ty   = tid >> 4;

    float acc[8][8];
#pragma unroll
    for (int i = 0; i < 8; i++)
#pragma unroll
        for (int j = 0; j < 8; j++) acc[i][j] = 0.0f;

    for (int k0 = 0; k0 < HID; k0 += 8) {
        float4 av = *(const float4*)(Ab + (size_t)lrow * HID + k0 + lk);
        float4 bv = *(const float4*)(Wb + (size_t)lrow * HID + k0 + lk);
        __syncthreads();
        As[lk + 0][lrow] = av.x; As[lk + 1][lrow] = av.y;
        As[lk + 2][lrow] = av.z; As[lk + 3][lrow] = av.w;
        Bs[lk + 0][lrow] = bv.x; Bs[lk + 1][lrow] = bv.y;
        Bs[lk + 2][lrow] = bv.z; Bs[lk + 3][lrow] = bv.w;
        __syncthreads();
#pragma unroll
        for (int kk = 0; kk < 8; kk++) {
            float a[8], b[8];
            *(float4*)&a[0] = *(const float4*)&As[kk][ty * 4];
            *(float4*)&a[4] = *(const float4*)&As[kk][64 + ty * 4];
            *(float4*)&b[0] = *(const float4*)&Bs[kk][tx * 4];
            *(float4*)&b[4] = *(const float4*)&Bs[kk][64 + tx * 4];
#pragma unroll
            for (int i = 0; i < 8; i++)
#pragma unroll
                for (int j = 0; j < 8; j++) acc[i][j] += a[i] * b[j];
        }
    }

#pragma unroll
    for (int i = 0; i < 8; i++) {
        const int row = bm * 128 + ((i < 4) ? (ty * 4 + i) : (64 + ty * 4 + i - 4));
#pragma unroll
        for (int jh = 0; jh < 2; jh++) {
            const int col = bn * 128 + jh * 64 + tx * 4;
            const float4 bb = *(const float4*)(bias + col);
            float4 r;
            r.x = acc[i][jh * 4 + 0] + bb.x;
            r.y = acc[i][jh * 4 + 1] + bb.y;
            r.z = acc[i][jh * 4 + 2] + bb.z;
            r.w = acc[i][jh * 4 + 3] + bb.w;
            *(float4*)(C + (size_t)row * HID + col) = r;
        }
    }
}

// ---------------------------------------------------------------------------
// Flash attention over groups. Block = one (b, h, 64-group q-tile).
// Group (g,d) <-> qlin row 2g + d/64, col h*64 + d%64.
// Q,K stored d-major (transposed) in smem for conflict-free score GEMM;
// V stored in natural seq-row layout for the P@V stage.
// Output ctx written to g_ctx linear layout: row 2g + h/8, col (h%8)*128 + d.
// ---------------------------------------------------------------------------
#define P68 68   // smem pitch (16B-aligned, decent bank spread)

__global__ __launch_bounds__(256) void attn_kernel(
    const float* __restrict__ qlin, const float* __restrict__ klin,
    const float* __restrict__ vlin, float* __restrict__ ctx)
{
    extern __shared__ float sm[];
    float* Qt = sm;                    // [128 d][64 i]  pitch P68
    float* Kt = Qt + 128 * P68;        // [128 d][64 j]
    float* Vs = Kt + 128 * P68;        // [128 row][64 col]
    float* Ps = Vs + 128 * P68;        // [64 i][64 j]
    float* row_m = Ps + 64 * P68;      // [64]
    float* row_l = row_m + 64;         // [64]
    float* row_a = row_l + 64;         // [64]

    const int tid = threadIdx.x;
    const int gt  = blockIdx.x;        // 0..15 q-tile
    const int h   = blockIdx.y;        // 0..15
    const int b   = blockIdx.z;        // 0..3
    const int g0  = gt * 64;
    const size_t bbase = (size_t)b * SEQ * HID;
    const float* qb = qlin + bbase;
    const float* kb = klin + bbase;
    const float* vb = vlin + bbase;
    const int hcol = h * 64;

    const int tx = tid & 15;           // S stage: j-block; PV stage: d-block
    const int ty = tid >> 4;           // i-block

    // --- load Q tile transposed: Qt[d][i] ---
    for (int idx = tid; idx < 64 * 32; idx += 256) {
        const int i  = idx >> 5;
        const int d  = (idx & 31) * 4;
        const int par = d >> 6;
        const int c   = d & 63;
        float4 v = *(const float4*)(qb + (size_t)(2 * (g0 + i) + par) * HID + hcol + c);
        Qt[(d + 0) * P68 + i] = v.x;
        Qt[(d + 1) * P68 + i] = v.y;
        Qt[(d + 2) * P68 + i] = v.z;
        Qt[(d + 3) * P68 + i] = v.w;
    }
    if (tid < 64) { row_m[tid] = -1e30f; row_l[tid] = 0.0f; }

    float o[4][8];
#pragma unroll
    for (int r = 0; r < 4; r++)
#pragma unroll
        for (int c = 0; c < 8; c++) o[r][c] = 0.0f;

    __syncthreads();

    for (int j0 = 0; j0 < NG; j0 += 64) {
        // --- load K chunk transposed, V chunk natural ---
        for (int idx = tid; idx < 64 * 32; idx += 256) {
            const int j  = idx >> 5;
            const int d  = (idx & 31) * 4;
            const int par = d >> 6;
            const int c   = d & 63;
            float4 v = *(const float4*)(kb + (size_t)(2 * (j0 + j) + par) * HID + hcol + c);
            Kt[(d + 0) * P68 + j] = v.x;
            Kt[(d + 1) * P68 + j] = v.y;
            Kt[(d + 2) * P68 + j] = v.z;
            Kt[(d + 3) * P68 + j] = v.w;
        }
        for (int idx = tid; idx < 128 * 16; idx += 256) {
            const int r  = idx >> 4;
            const int c4 = (idx & 15) * 4;
            float4 v = *(const float4*)(vb + (size_t)(2 * j0 + r) * HID + hcol + c4);
            *(float4*)&Vs[r * P68 + c4] = v;
        }
        __syncthreads();

        // --- scores S[i,j] = sum_d Q[i,d] K[j,d], i=ty*4+., j=tx*4+. ---
        float sacc[4][4];
#pragma unroll
        for (int r = 0; r < 4; r++)
#pragma unroll
            for (int j = 0; j < 4; j++) sacc[r][j] = 0.0f;

#pragma unroll 4
        for (int d = 0; d < 128; d++) {
            float4 qa = *(const float4*)&Qt[d * P68 + ty * 4];
            float4 kk = *(const float4*)&Kt[d * P68 + tx * 4];
            const float qv[4] = {qa.x, qa.y, qa.z, qa.w};
            const float kv[4] = {kk.x, kk.y, kk.z, kk.w};
#pragma unroll
            for (int r = 0; r < 4; r++)
#pragma unroll
                for (int j = 0; j < 4; j++) sacc[r][j] += qv[r] * kv[j];
        }
#pragma unroll
        for (int r = 0; r < 4; r++)
#pragma unroll
            for (int j = 0; j < 4; j++)
                Ps[(ty * 4 + r) * P68 + tx * 4 + j] = sacc[r][j] * SCALE;
        __syncthreads();

        // --- online softmax, one thread per row ---
        if (tid < 64) {
            const int i = tid;
            float mc = -1e30f;
#pragma unroll 8
            for (int j = 0; j < 64; j++) mc = fmaxf(mc, Ps[i * P68 + j]);
            const float m_old = row_m[i];
            const float m_new = fmaxf(m_old, mc);
            const float alpha = __expf(m_old - m_new);
            float l = row_l[i] * alpha;
#pragma unroll 8
            for (int j = 0; j < 64; j++) {
                const float p = __expf(Ps[i * P68 + j] - m_new);
                Ps[i * P68 + j] = p;
                l += p;
            }
            row_m[i] = m_new;
            row_l[i] = l;
            row_a[i] = alpha;
        }
        __syncthreads();

        // --- rescale O, accumulate P @ V. thread: rows ty*4+r, cols tx*8+dd ---
        {
            float al[4];
#pragma unroll
            for (int r = 0; r < 4; r++) al[r] = row_a[ty * 4 + r];
#pragma unroll
            for (int r = 0; r < 4; r++)
#pragma unroll
                for (int c = 0; c < 8; c++) o[r][c] *= al[r];

            const int vr_par = (tx >> 3);          // d >= 64 ?
            const int vcol   = (tx & 7) * 8;
#pragma unroll 2
            for (int j = 0; j < 64; j++) {
                const float* vp = &Vs[(2 * j + vr_par) * P68 + vcol];
                float4 v0 = *(const float4*)vp;
                float4 v1 = *(const float4*)(vp + 4);
                float p[4];
#pragma unroll
                for (int r = 0; r < 4; r++) p[r] = Ps[(ty * 4 + r) * P68 + j];
#pragma unroll
                for (int r = 0; r < 4; r++) {
                    o[r][0] += p[r] * v0.x; o[r][1] += p[r] * v0.y;
                    o[r][2] += p[r] * v0.z; o[r][3] += p[r] * v0.w;
                    o[r][4] += p[r] * v1.x; o[r][5] += p[r] * v1.y;
                    o[r][6] += p[r] * v1.z; o[r][7] += p[r] * v1.w;
                }
            }
        }
        __syncthreads();   // protect Kt/Vs/Ps for next chunk
    }

    // --- epilogue: normalize & scatter to linear ctx layout ---
    float* cb = ctx + bbase;
#pragma unroll
    for (int r = 0; r < 4; r++) {
        const int i = ty * 4 + r;
        const float inv = 1.0f / row_l[i];
        const int g = g0 + i;
        const int orow = 2 * g + (h >> 3);
        const int ocol = (h & 7) * 128 + tx * 8;
        float4 w0, w1;
        w0.x = o[r][0] * inv; w0.y = o[r][1] * inv;
        w0.z = o[r][2] * inv; w0.w = o[r][3] * inv;
        w1.x = o[r][4] * inv; w1.y = o[r][5] * inv;
        w1.z = o[r][6] * inv; w1.w = o[r][7] * inv;
        *(float4*)(cb + (size_t)orow * HID + ocol)     = w0;
        *(float4*)(cb + (size_t)orow * HID + ocol + 4) = w1;
    }
}

// ---------------------------------------------------------------------------
extern "C" void kernel_launch(void* const* d_in, const int* in_sizes, int n_in,
                              void* d_out, int out_size)
{
    const float* x  = (const float*)d_in[0];
    const float* Wq = (const float*)d_in[1];
    const float* bq = (const float*)d_in[2];
    const float* Wk = (const float*)d_in[3];
    const float* bk = (const float*)d_in[4];
    const float* Wv = (const float*)d_in[5];
    const float* bv = (const float*)d_in[6];
    const float* Wo = (const float*)d_in[7];
    const float* bo = (const float*)d_in[8];
    float* out = (float*)d_out;

    float *q, *k, *v, *ctx;
    cudaGetSymbolAddress((void**)&q,   g_q);
    cudaGetSymbolAddress((void**)&k,   g_k);
    cudaGetSymbolAddress((void**)&v,   g_v);
    cudaGetSymbolAddress((void**)&ctx, g_ctx);

    const dim3 gemm_grid(HID / 128, M_TOT / 128);   // (8, 64)
    sgemm_nt_bias<<<gemm_grid, 256>>>(x, Wq, bq, q);
    sgemm_nt_bias<<<gemm_grid, 256>>>(x, Wk, bk, k);
    sgemm_nt_bias<<<gemm_grid, 256>>>(x, Wv, bv, v);

    const int smem_bytes = (3 * 128 * P68 + 64 * P68 + 3 * 64) * (int)sizeof(float);
    cudaFuncSetAttribute(attn_kernel,
                         cudaFuncAttributeMaxDynamicSharedMemorySize, smem_bytes);
    attn_kernel<<<dim3(NG / 64, NH, BATCH), 256, smem_bytes>>>(q, k, v, ctx);

    sgemm_nt_bias<<<gemm_grid, 256>>>(ctx, Wo, bo, out);
}

// round 5
// speedup vs baseline: 1.5033x; 1.4997x over previous
#include <cuda_runtime.h>
#include <stdint.h>

// Problem dims (compile-time)
#define HID   1024
#define SEQ   2048
#define BATCH 4
#define NH    16
#define NG    1024
#define M_TOT (BATCH * SEQ)   // 8192
#define SCALE 0.125f          // 1/sqrt(64)

// Scratch: linear [B,S,HID] fp32 buffers (static device arrays — no allocs)
__device__ float g_q[(size_t)M_TOT * HID];
__device__ float g_k[(size_t)M_TOT * HID];
__device__ float g_v[(size_t)M_TOT * HID];
__device__ float g_ctx[(size_t)M_TOT * HID];

// ===========================================================================
// helpers
// ===========================================================================
__device__ __forceinline__ uint32_t smem_u32(const void* p) {
    uint32_t a;
    asm("{ .reg .u64 t; cvta.to.shared.u64 t, %1; cvt.u32.u64 %0, t; }"
        : "=r"(a) : "l"(p));
    return a;
}

__device__ __forceinline__ void cp16(uint32_t dst, const void* src) {
    asm volatile("cp.async.cg.shared.global [%0], [%1], 16;\n"
                 :: "r"(dst), "l"(src));
}
#define CP_COMMIT() asm volatile("cp.async.commit_group;\n" ::: "memory")

__device__ __forceinline__ uint32_t f2tf32(float x) {
    uint32_t r;
    asm("cvt.rna.tf32.f32 %0, %1;" : "=r"(r) : "f"(x));
    return r;
}

// mma.sync m16n8k8 tf32: D += A(16x8 row) * B(8x8 col)
__device__ __forceinline__ void mma_tf32(float* c, const uint32_t* a, const uint32_t* b) {
    asm volatile(
        "mma.sync.aligned.m16n8k8.row.col.f32.tf32.tf32.f32 "
        "{%0,%1,%2,%3}, {%4,%5,%6,%7}, {%8,%9}, {%0,%1,%2,%3};\n"
        : "+f"(c[0]), "+f"(c[1]), "+f"(c[2]), "+f"(c[3])
        : "r"(a[0]), "r"(a[1]), "r"(a[2]), "r"(a[3]), "r"(b[0]), "r"(b[1]));
}

// ===========================================================================
// tf32 mma.sync GEMM (NT): C[m,n] = sum_k A[m,k] * W[n,k] + bias[n]
// CTA tile 128x128, 256 threads (8 warps), warp tile 32x64 (2 m-frags x 8
// n-frags of m16n8k8). K-chunks of 32, 2-stage cp.async double buffer.
// Smem pitch 36 floats -> conflict-free fragment LDS (bank = lane + const).
// ===========================================================================
#define KC        32
#define NCHUNK    (HID / KC)             // 32
#define GPITCH    36                     // floats per smem row (144 B)
#define OP_FLOATS (128 * GPITCH)         // one operand: 18432 B
#define STAGE_FLOATS (2 * OP_FLOATS)     // A + B: 36864 B
#define GEMM_SMEM (2 * STAGE_FLOATS * 4) // 73728 B

__global__ __launch_bounds__(256) void gemm_tf32_nt_bias(
    const float* __restrict__ A, const float* __restrict__ W,
    const float* __restrict__ bias, float* __restrict__ C)
{
    extern __shared__ __align__(16) float smem[];
    const int tid  = threadIdx.x;
    const int wid  = tid >> 5;
    const int lane = tid & 31;
    const int bn   = blockIdx.x;   // 0..7
    const int bm   = blockIdx.y;   // 0..63

    const int wy = wid >> 1;       // 0..3 -> m offset wy*32
    const int wx = wid & 1;        // 0..1 -> n offset wx*64
    const int qid = lane >> 2;     // lane/4
    const int rid = lane & 3;      // lane%4

    const uint32_t sbase = smem_u32(smem);
    const float* Ab = A + (size_t)bm * 128 * HID;
    const float* Wb = W + (size_t)bn * 128 * HID;

    // chunk loader: per operand 128 rows x 32 floats (8 x 16B per row)
    auto load_chunk = [&](int c, int s) {
        const uint32_t sa = sbase + (uint32_t)(s * STAGE_FLOATS) * 4u;
        const uint32_t sb = sa + (uint32_t)OP_FLOATS * 4u;
        const int k0 = c * KC;
#pragma unroll
        for (int p = 0; p < 4; p++) {
            const int idx = tid + p * 256;
            const int r  = idx >> 3;
            const int cc = idx & 7;
            const uint32_t off = (uint32_t)(r * GPITCH + cc * 4) * 4u;
            const size_t gsrc = (size_t)r * HID + k0 + cc * 4;
            cp16(sa + off, Ab + gsrc);
            cp16(sb + off, Wb + gsrc);
        }
        CP_COMMIT();
    };

    float cacc[2][8][4];
#pragma unroll
    for (int mt = 0; mt < 2; mt++)
#pragma unroll
        for (int nt = 0; nt < 8; nt++)
#pragma unroll
            for (int e = 0; e < 4; e++) cacc[mt][nt][e] = 0.0f;

    load_chunk(0, 0);
    int s = 0;

    for (int c = 0; c < NCHUNK; c++) {
        if (c + 1 < NCHUNK) {
            load_chunk(c + 1, s ^ 1);
            asm volatile("cp.async.wait_group 1;\n" ::: "memory");
        } else {
            asm volatile("cp.async.wait_group 0;\n" ::: "memory");
        }
        __syncthreads();

        const float* As = smem + s * STAGE_FLOATS;
        const float* Bs = As + OP_FLOATS;

#pragma unroll
        for (int ks = 0; ks < 4; ks++) {
            const int k0 = ks * 8;
            uint32_t afr[2][4];
#pragma unroll
            for (int mt = 0; mt < 2; mt++) {
                const int row = wy * 32 + mt * 16 + qid;
                afr[mt][0] = f2tf32(As[(row    ) * GPITCH + k0 + rid    ]);
                afr[mt][1] = f2tf32(As[(row + 8) * GPITCH + k0 + rid    ]);
                afr[mt][2] = f2tf32(As[(row    ) * GPITCH + k0 + rid + 4]);
                afr[mt][3] = f2tf32(As[(row + 8) * GPITCH + k0 + rid + 4]);
            }
            uint32_t bfr[8][2];
#pragma unroll
            for (int nt = 0; nt < 8; nt++) {
                const int n = wx * 64 + nt * 8 + qid;
                bfr[nt][0] = f2tf32(Bs[n * GPITCH + k0 + rid    ]);
                bfr[nt][1] = f2tf32(Bs[n * GPITCH + k0 + rid + 4]);
            }
#pragma unroll
            for (int mt = 0; mt < 2; mt++)
#pragma unroll
                for (int nt = 0; nt < 8; nt++)
                    mma_tf32(cacc[mt][nt], afr[mt], bfr[nt]);
        }
        __syncthreads();
        s ^= 1;
    }

    // epilogue: c0,c1 -> (row, col..col+1); c2,c3 -> (row+8, ...)
#pragma unroll
    for (int mt = 0; mt < 2; mt++) {
        const int row0 = bm * 128 + wy * 32 + mt * 16 + qid;
#pragma unroll
        for (int nt = 0; nt < 8; nt++) {
            const int col = bn * 128 + wx * 64 + nt * 8 + rid * 2;
            const float b0 = bias[col];
            const float b1 = bias[col + 1];
            float2 r0, r1;
            r0.x = cacc[mt][nt][0] + b0; r0.y = cacc[mt][nt][1] + b1;
            r1.x = cacc[mt][nt][2] + b0; r1.y = cacc[mt][nt][3] + b1;
            *(float2*)(C + (size_t)row0 * HID + col)       = r0;
            *(float2*)(C + (size_t)(row0 + 8) * HID + col) = r1;
        }
    }
}

// ---------------------------------------------------------------------------
// Flash attention over groups (unchanged from passing R1 kernel).
// ---------------------------------------------------------------------------
#define P68 68   // smem pitch

__global__ __launch_bounds__(256) void attn_kernel(
    const float* __restrict__ qlin, const float* __restrict__ klin,
    const float* __restrict__ vlin, float* __restrict__ ctx)
{
    extern __shared__ float sm[];
    float* Qt = sm;                    // [128 d][64 i]  pitch P68
    float* Kt = Qt + 128 * P68;        // [128 d][64 j]
    float* Vs = Kt + 128 * P68;        // [128 row][64 col]
    float* Ps = Vs + 128 * P68;        // [64 i][64 j]
    float* row_m = Ps + 64 * P68;
    float* row_l = row_m + 64;
    float* row_a = row_l + 64;

    const int tid = threadIdx.x;
    const int gt  = blockIdx.x;
    const int h   = blockIdx.y;
    const int b   = blockIdx.z;
    const int g0  = gt * 64;
    const size_t bbase = (size_t)b * SEQ * HID;
    const float* qb = qlin + bbase;
    const float* kb = klin + bbase;
    const float* vb = vlin + bbase;
    const int hcol = h * 64;

    const int tx = tid & 15;
    const int ty = tid >> 4;

    for (int idx = tid; idx < 64 * 32; idx += 256) {
        const int i  = idx >> 5;
        const int d  = (idx & 31) * 4;
        const int par = d >> 6;
        const int c   = d & 63;
        float4 v = *(const float4*)(qb + (size_t)(2 * (g0 + i) + par) * HID + hcol + c);
        Qt[(d + 0) * P68 + i] = v.x;
        Qt[(d + 1) * P68 + i] = v.y;
        Qt[(d + 2) * P68 + i] = v.z;
        Qt[(d + 3) * P68 + i] = v.w;
    }
    if (tid < 64) { row_m[tid] = -1e30f; row_l[tid] = 0.0f; }

    float o[4][8];
#pragma unroll
    for (int r = 0; r < 4; r++)
#pragma unroll
        for (int c = 0; c < 8; c++) o[r][c] = 0.0f;

    __syncthreads();

    for (int j0 = 0; j0 < NG; j0 += 64) {
        for (int idx = tid; idx < 64 * 32; idx += 256) {
            const int j  = idx >> 5;
            const int d  = (idx & 31) * 4;
            const int par = d >> 6;
            const int c   = d & 63;
            float4 v = *(const float4*)(kb + (size_t)(2 * (j0 + j) + par) * HID + hcol + c);
            Kt[(d + 0) * P68 + j] = v.x;
            Kt[(d + 1) * P68 + j] = v.y;
            Kt[(d + 2) * P68 + j] = v.z;
            Kt[(d + 3) * P68 + j] = v.w;
        }
        for (int idx = tid; idx < 128 * 16; idx += 256) {
            const int r  = idx >> 4;
            const int c4 = (idx & 15) * 4;
            float4 v = *(const float4*)(vb + (size_t)(2 * j0 + r) * HID + hcol + c4);
            *(float4*)&Vs[r * P68 + c4] = v;
        }
        __syncthreads();

        float sacc[4][4];
#pragma unroll
        for (int r = 0; r < 4; r++)
#pragma unroll
            for (int j = 0; j < 4; j++) sacc[r][j] = 0.0f;

#pragma unroll 4
        for (int d = 0; d < 128; d++) {
            float4 qa = *(const float4*)&Qt[d * P68 + ty * 4];
            float4 kk = *(const float4*)&Kt[d * P68 + tx * 4];
            const float qv[4] = {qa.x, qa.y, qa.z, qa.w};
            const float kv[4] = {kk.x, kk.y, kk.z, kk.w};
#pragma unroll
            for (int r = 0; r < 4; r++)
#pragma unroll
                for (int j = 0; j < 4; j++) sacc[r][j] += qv[r] * kv[j];
        }
#pragma unroll
        for (int r = 0; r < 4; r++)
#pragma unroll
            for (int j = 0; j < 4; j++)
                Ps[(ty * 4 + r) * P68 + tx * 4 + j] = sacc[r][j] * SCALE;
        __syncthreads();

        if (tid < 64) {
            const int i = tid;
            float mc = -1e30f;
#pragma unroll 8
            for (int j = 0; j < 64; j++) mc = fmaxf(mc, Ps[i * P68 + j]);
            const float m_old = row_m[i];
            const float m_new = fmaxf(m_old, mc);
            const float alpha = __expf(m_old - m_new);
            float l = row_l[i] * alpha;
#pragma unroll 8
            for (int j = 0; j < 64; j++) {
                const float p = __expf(Ps[i * P68 + j] - m_new);
                Ps[i * P68 + j] = p;
                l += p;
            }
            row_m[i] = m_new;
            row_l[i] = l;
            row_a[i] = alpha;
        }
        __syncthreads();

        {
            float al[4];
#pragma unroll
            for (int r = 0; r < 4; r++) al[r] = row_a[ty * 4 + r];
#pragma unroll
            for (int r = 0; r < 4; r++)
#pragma unroll
                for (int c = 0; c < 8; c++) o[r][c] *= al[r];

            const int vr_par = (tx >> 3);
            const int vcol   = (tx & 7) * 8;
#pragma unroll 2
            for (int j = 0; j < 64; j++) {
                const float* vp = &Vs[(2 * j + vr_par) * P68 + vcol];
                float4 v0 = *(const float4*)vp;
                float4 v1 = *(const float4*)(vp + 4);
                float p[4];
#pragma unroll
                for (int r = 0; r < 4; r++) p[r] = Ps[(ty * 4 + r) * P68 + j];
#pragma unroll
                for (int r = 0; r < 4; r++) {
                    o[r][0] += p[r] * v0.x; o[r][1] += p[r] * v0.y;
                    o[r][2] += p[r] * v0.z; o[r][3] += p[r] * v0.w;
                    o[r][4] += p[r] * v1.x; o[r][5] += p[r] * v1.y;
                    o[r][6] += p[r] * v1.z; o[r][7] += p[r] * v1.w;
                }
            }
        }
        __syncthreads();
    }

    float* cb = ctx + bbase;
#pragma unroll
    for (int r = 0; r < 4; r++) {
        const int i = ty * 4 + r;
        const float inv = 1.0f / row_l[i];
        const int g = g0 + i;
        const int orow = 2 * g + (h >> 3);
        const int ocol = (h & 7) * 128 + tx * 8;
        float4 w0, w1;
        w0.x = o[r][0] * inv; w0.y = o[r][1] * inv;
        w0.z = o[r][2] * inv; w0.w = o[r][3] * inv;
        w1.x = o[r][4] * inv; w1.y = o[r][5] * inv;
        w1.z = o[r][6] * inv; w1.w = o[r][7] * inv;
        *(float4*)(cb + (size_t)orow * HID + ocol)     = w0;
        *(float4*)(cb + (size_t)orow * HID + ocol + 4) = w1;
    }
}

// ---------------------------------------------------------------------------
extern "C" void kernel_launch(void* const* d_in, const int* in_sizes, int n_in,
                              void* d_out, int out_size)
{
    const float* x  = (const float*)d_in[0];
    const float* Wq = (const float*)d_in[1];
    const float* bq = (const float*)d_in[2];
    const float* Wk = (const float*)d_in[3];
    const float* bk = (const float*)d_in[4];
    const float* Wv = (const float*)d_in[5];
    const float* bv = (const float*)d_in[6];
    const float* Wo = (const float*)d_in[7];
    const float* bo = (const float*)d_in[8];
    float* out = (float*)d_out;

    float *q, *k, *v, *ctx;
    cudaGetSymbolAddress((void**)&q,   g_q);
    cudaGetSymbolAddress((void**)&k,   g_k);
    cudaGetSymbolAddress((void**)&v,   g_v);
    cudaGetSymbolAddress((void**)&ctx, g_ctx);

    cudaFuncSetAttribute(gemm_tf32_nt_bias,
                         cudaFuncAttributeMaxDynamicSharedMemorySize, GEMM_SMEM);

    const dim3 gemm_grid(HID / 128, M_TOT / 128);   // (8, 64)
    gemm_tf32_nt_bias<<<gemm_grid, 256, GEMM_SMEM>>>(x, Wq, bq, q);
    gemm_tf32_nt_bias<<<gemm_grid, 256, GEMM_SMEM>>>(x, Wk, bk, k);
    gemm_tf32_nt_bias<<<gemm_grid, 256, GEMM_SMEM>>>(x, Wv, bv, v);

    const int attn_smem = (3 * 128 * P68 + 64 * P68 + 3 * 64) * (int)sizeof(float);
    cudaFuncSetAttribute(attn_kernel,
                         cudaFuncAttributeMaxDynamicSharedMemorySize, attn_smem);
    attn_kernel<<<dim3(NG / 64, NH, BATCH), 256, attn_smem>>>(q, k, v, ctx);

    gemm_tf32_nt_bias<<<gemm_grid, 256, GEMM_SMEM>>>(ctx, Wo, bo, out);
}

// round 6
// speedup vs baseline: 3.0529x; 2.0308x over previous
#include <cuda_runtime.h>
#include <stdint.h>

// Problem dims (compile-time)
#define HID   1024
#define SEQ   2048
#define BATCH 4
#define NH    16
#define NG    1024
#define M_TOT (BATCH * SEQ)   // 8192
#define SCALE 0.125f          // 1/sqrt(64)

// Scratch: linear [B,S,HID] fp32 buffers (static device arrays — no allocs)
__device__ float g_q[(size_t)M_TOT * HID];
__device__ float g_k[(size_t)M_TOT * HID];
__device__ float g_v[(size_t)M_TOT * HID];
__device__ float g_ctx[(size_t)M_TOT * HID];

// ===========================================================================
// helpers
// ===========================================================================
__device__ __forceinline__ uint32_t smem_u32(const void* p) {
    uint32_t a;
    asm("{ .reg .u64 t; cvta.to.shared.u64 t, %1; cvt.u32.u64 %0, t; }"
        : "=r"(a) : "l"(p));
    return a;
}

__device__ __forceinline__ void cp16(uint32_t dst, const void* src) {
    asm volatile("cp.async.cg.shared.global [%0], [%1], 16;\n"
                 :: "r"(dst), "l"(src));
}
#define CP_COMMIT() asm volatile("cp.async.commit_group;\n" ::: "memory")

__device__ __forceinline__ uint32_t f2tf32(float x) {
    uint32_t r;
    asm("cvt.rna.tf32.f32 %0, %1;" : "=r"(r) : "f"(x));
    return r;
}

// mma.sync m16n8k8 tf32: D += A(16x8 row) * B(8x8 col)
__device__ __forceinline__ void mma_tf32(float* c, const uint32_t* a, const uint32_t* b) {
    asm volatile(
        "mma.sync.aligned.m16n8k8.row.col.f32.tf32.tf32.f32 "
        "{%0,%1,%2,%3}, {%4,%5,%6,%7}, {%8,%9}, {%0,%1,%2,%3};\n"
        : "+f"(c[0]), "+f"(c[1]), "+f"(c[2]), "+f"(c[3])
        : "r"(a[0]), "r"(a[1]), "r"(a[2]), "r"(a[3]), "r"(b[0]), "r"(b[1]));
}

// ===========================================================================
// tf32 mma.sync GEMM (NT): C[m,n] = sum_k A[m,k] * W[n,k] + bias[n]
// (unchanged from R4 passing kernel)
// ===========================================================================
#define KC        32
#define NCHUNK    (HID / KC)             // 32
#define GPITCH    36
#define OP_FLOATS (128 * GPITCH)
#define STAGE_FLOATS (2 * OP_FLOATS)
#define GEMM_SMEM (2 * STAGE_FLOATS * 4) // 73728 B

__global__ __launch_bounds__(256) void gemm_tf32_nt_bias(
    const float* __restrict__ A, const float* __restrict__ W,
    const float* __restrict__ bias, float* __restrict__ C)
{
    extern __shared__ __align__(16) float smem[];
    const int tid  = threadIdx.x;
    const int wid  = tid >> 5;
    const int lane = tid & 31;
    const int bn   = blockIdx.x;
    const int bm   = blockIdx.y;

    const int wy = wid >> 1;
    const int wx = wid & 1;
    const int qid = lane >> 2;
    const int rid = lane & 3;

    const uint32_t sbase = smem_u32(smem);
    const float* Ab = A + (size_t)bm * 128 * HID;
    const float* Wb = W + (size_t)bn * 128 * HID;

    auto load_chunk = [&](int c, int s) {
        const uint32_t sa = sbase + (uint32_t)(s * STAGE_FLOATS) * 4u;
        const uint32_t sb = sa + (uint32_t)OP_FLOATS * 4u;
        const int k0 = c * KC;
#pragma unroll
        for (int p = 0; p < 4; p++) {
            const int idx = tid + p * 256;
            const int r  = idx >> 3;
            const int cc = idx & 7;
            const uint32_t off = (uint32_t)(r * GPITCH + cc * 4) * 4u;
            const size_t gsrc = (size_t)r * HID + k0 + cc * 4;
            cp16(sa + off, Ab + gsrc);
            cp16(sb + off, Wb + gsrc);
        }
        CP_COMMIT();
    };

    float cacc[2][8][4];
#pragma unroll
    for (int mt = 0; mt < 2; mt++)
#pragma unroll
        for (int nt = 0; nt < 8; nt++)
#pragma unroll
            for (int e = 0; e < 4; e++) cacc[mt][nt][e] = 0.0f;

    load_chunk(0, 0);
    int s = 0;

    for (int c = 0; c < NCHUNK; c++) {
        if (c + 1 < NCHUNK) {
            load_chunk(c + 1, s ^ 1);
            asm volatile("cp.async.wait_group 1;\n" ::: "memory");
        } else {
            asm volatile("cp.async.wait_group 0;\n" ::: "memory");
        }
        __syncthreads();

        const float* As = smem + s * STAGE_FLOATS;
        const float* Bs = As + OP_FLOATS;

#pragma unroll
        for (int ks = 0; ks < 4; ks++) {
            const int k0 = ks * 8;
            uint32_t afr[2][4];
#pragma unroll
            for (int mt = 0; mt < 2; mt++) {
                const int row = wy * 32 + mt * 16 + qid;
                afr[mt][0] = f2tf32(As[(row    ) * GPITCH + k0 + rid    ]);
                afr[mt][1] = f2tf32(As[(row + 8) * GPITCH + k0 + rid    ]);
                afr[mt][2] = f2tf32(As[(row    ) * GPITCH + k0 + rid + 4]);
                afr[mt][3] = f2tf32(As[(row + 8) * GPITCH + k0 + rid + 4]);
            }
            uint32_t bfr[8][2];
#pragma unroll
            for (int nt = 0; nt < 8; nt++) {
                const int n = wx * 64 + nt * 8 + qid;
                bfr[nt][0] = f2tf32(Bs[n * GPITCH + k0 + rid    ]);
                bfr[nt][1] = f2tf32(Bs[n * GPITCH + k0 + rid + 4]);
            }
#pragma unroll
            for (int mt = 0; mt < 2; mt++)
#pragma unroll
                for (int nt = 0; nt < 8; nt++)
                    mma_tf32(cacc[mt][nt], afr[mt], bfr[nt]);
        }
        __syncthreads();
        s ^= 1;
    }

#pragma unroll
    for (int mt = 0; mt < 2; mt++) {
        const int row0 = bm * 128 + wy * 32 + mt * 16 + qid;
#pragma unroll
        for (int nt = 0; nt < 8; nt++) {
            const int col = bn * 128 + wx * 64 + nt * 8 + rid * 2;
            const float b0 = bias[col];
            const float b1 = bias[col + 1];
            float2 r0, r1;
            r0.x = cacc[mt][nt][0] + b0; r0.y = cacc[mt][nt][1] + b1;
            r1.x = cacc[mt][nt][2] + b0; r1.y = cacc[mt][nt][3] + b1;
            *(float2*)(C + (size_t)row0 * HID + col)       = r0;
            *(float2*)(C + (size_t)(row0 + 8) * HID + col) = r1;
        }
    }
}

// ===========================================================================
// Tensor-core flash attention over groups.
// Block = (b, h, 64-group q-tile). 256 threads / 8 warps.
// Group (g,d) <-> lin row 2g + d/64, col h*64 + d%64 (d in [0,128)).
// Warp w: S rows 16*(w%4), S col-half 32*(w/4); PV rows same, d-half 64*(w/4).
// K/V chunks (64 groups) double-buffered via cp.async.
// ===========================================================================
#define QP 132   // pitch for Qs/Ks/Vs rows of 128 floats
#define PP 68    // pitch for Ps (64 cols)

#define SM_QS   0
#define SM_KS   (SM_QS + 64 * QP)            // 2 stages
#define SM_VS   (SM_KS + 2 * 64 * QP)        // 2 stages
#define SM_PS   (SM_VS + 2 * 64 * QP)
#define SM_RM   (SM_PS + 64 * PP)
#define SM_RL   (SM_RM + 64)
#define SM_PM   (SM_RL + 64)                 // [2][64]
#define SM_PSUM (SM_PM + 128)                // [2][64]
#define ATTN_FLOATS (SM_PSUM + 128)
#define ATTN_SMEM (ATTN_FLOATS * 4)

__global__ __launch_bounds__(256) void attn_kernel(
    const float* __restrict__ qlin, const float* __restrict__ klin,
    const float* __restrict__ vlin, float* __restrict__ ctx)
{
    extern __shared__ __align__(16) float sm[];
    float* Qs = sm + SM_QS;
    float* Ks = sm + SM_KS;
    float* Vs = sm + SM_VS;
    float* Ps = sm + SM_PS;
    float* row_m = sm + SM_RM;
    float* row_l = sm + SM_RL;
    float* pmax  = sm + SM_PM;
    float* psum  = sm + SM_PSUM;

    const int tid  = threadIdx.x;
    const int wid  = tid >> 5;
    const int lane = tid & 31;
    const int qid  = lane >> 2;
    const int rid  = lane & 3;
    const int r0   = 16 * (wid & 3);     // S/PV row base
    const int ch   = wid >> 2;           // col-half (S) / d-half (PV)
    const int rlo  = r0 + qid;
    const int rhi  = rlo + 8;

    const int gt = blockIdx.x;
    const int h  = blockIdx.y;
    const int b  = blockIdx.z;
    const int g0 = gt * 64;
    const size_t bbase = (size_t)b * SEQ * HID;
    const float* qb = qlin + bbase;
    const float* kb = klin + bbase;
    const float* vb = vlin + bbase;
    const int hcol = h * 64;

    const uint32_t sbase = smem_u32(sm);
    const uint32_t qs_a = sbase + SM_QS * 4u;

    // --- Q load (cp.async): 64 rows x 128 floats ---
#pragma unroll
    for (int p = 0; p < 8; p++) {
        const int idx = tid + p * 256;
        const int i   = idx >> 5;
        const int d4  = (idx & 31) * 4;
        const int par = d4 >> 6;
        const int cc  = d4 & 63;
        cp16(qs_a + (uint32_t)(i * QP + d4) * 4u,
             qb + (size_t)(2 * (g0 + i) + par) * HID + hcol + cc);
    }
    CP_COMMIT();

    auto loadKV = [&](int c, int s) {
        const uint32_t ka = sbase + (SM_KS + s * 64 * QP) * 4u;
        const uint32_t va = sbase + (SM_VS + s * 64 * QP) * 4u;
        const int j0 = c * 64;
#pragma unroll
        for (int p = 0; p < 8; p++) {
            const int idx = tid + p * 256;
            const int j   = idx >> 5;
            const int d4  = (idx & 31) * 4;
            const int par = d4 >> 6;
            const int cc  = d4 & 63;
            const size_t gs = (size_t)(2 * (j0 + j) + par) * HID + hcol + cc;
            const uint32_t off = (uint32_t)(j * QP + d4) * 4u;
            cp16(ka + off, kb + gs);
            cp16(va + off, vb + gs);
        }
        CP_COMMIT();
    };

    loadKV(0, 0);

    if (tid < 64) { row_m[tid] = -1e30f; row_l[tid] = 0.0f; }

    float o[8][4];
#pragma unroll
    for (int nt = 0; nt < 8; nt++)
#pragma unroll
        for (int e = 0; e < 4; e++) o[nt][e] = 0.0f;

    for (int c = 0; c < 16; c++) {
        const int s = c & 1;
        if (c + 1 < 16) {
            loadKV(c + 1, s ^ 1);
            asm volatile("cp.async.wait_group 1;\n" ::: "memory");
        } else {
            asm volatile("cp.async.wait_group 0;\n" ::: "memory");
        }
        __syncthreads();

        const float* Kst = Ks + s * 64 * QP;
        const float* Vst = Vs + s * 64 * QP;

        // --- S = Q * K^T (this warp: rows r0..r0+15, cols ch*32..+31) ---
        float sacc[4][4];
#pragma unroll
        for (int nt = 0; nt < 4; nt++)
#pragma unroll
            for (int e = 0; e < 4; e++) sacc[nt][e] = 0.0f;

#pragma unroll
        for (int ks = 0; ks < 16; ks++) {
            const int k0 = ks * 8;
            uint32_t afr[4];
            afr[0] = f2tf32(Qs[rlo * QP + k0 + rid    ]);
            afr[1] = f2tf32(Qs[rhi * QP + k0 + rid    ]);
            afr[2] = f2tf32(Qs[rlo * QP + k0 + rid + 4]);
            afr[3] = f2tf32(Qs[rhi * QP + k0 + rid + 4]);
            uint32_t bfr[4][2];
#pragma unroll
            for (int nt = 0; nt < 4; nt++) {
                const int n = ch * 32 + nt * 8 + qid;
                bfr[nt][0] = f2tf32(Kst[n * QP + k0 + rid    ]);
                bfr[nt][1] = f2tf32(Kst[n * QP + k0 + rid + 4]);
            }
#pragma unroll
            for (int nt = 0; nt < 4; nt++)
                mma_tf32(sacc[nt], afr, bfr[nt]);
        }
#pragma unroll
        for (int nt = 0; nt < 4; nt++)
#pragma unroll
            for (int e = 0; e < 4; e++) sacc[nt][e] *= SCALE;

        // --- register softmax: quad-reduce row max, smem-combine halves ---
        float mlo = -1e30f, mhi = -1e30f;
#pragma unroll
        for (int nt = 0; nt < 4; nt++) {
            mlo = fmaxf(mlo, fmaxf(sacc[nt][0], sacc[nt][1]));
            mhi = fmaxf(mhi, fmaxf(sacc[nt][2], sacc[nt][3]));
        }
        mlo = fmaxf(mlo, __shfl_xor_sync(0xffffffffu, mlo, 1));
        mlo = fmaxf(mlo, __shfl_xor_sync(0xffffffffu, mlo, 2));
        mhi = fmaxf(mhi, __shfl_xor_sync(0xffffffffu, mhi, 1));
        mhi = fmaxf(mhi, __shfl_xor_sync(0xffffffffu, mhi, 2));
        if (rid == 0) {
            pmax[ch * 64 + rlo] = mlo;
            pmax[ch * 64 + rhi] = mhi;
        }
        __syncthreads();

        const float mo_lo = row_m[rlo];
        const float mo_hi = row_m[rhi];
        const float mn_lo = fmaxf(mo_lo, fmaxf(pmax[rlo], pmax[64 + rlo]));
        const float mn_hi = fmaxf(mo_hi, fmaxf(pmax[rhi], pmax[64 + rhi]));
        const float al_lo = __expf(mo_lo - mn_lo);
        const float al_hi = __expf(mo_hi - mn_hi);

        float slo = 0.0f, shi = 0.0f;
#pragma unroll
        for (int nt = 0; nt < 4; nt++) {
            float p0 = __expf(sacc[nt][0] - mn_lo);
            float p1 = __expf(sacc[nt][1] - mn_lo);
            float p2 = __expf(sacc[nt][2] - mn_hi);
            float p3 = __expf(sacc[nt][3] - mn_hi);
            sacc[nt][0] = p0; sacc[nt][1] = p1;
            sacc[nt][2] = p2; sacc[nt][3] = p3;
            slo += p0 + p1;
            shi += p2 + p3;
            const int col = ch * 32 + nt * 8 + rid * 2;
            *(float2*)&Ps[rlo * PP + col] = make_float2(p0, p1);
            *(float2*)&Ps[rhi * PP + col] = make_float2(p2, p3);
        }
        slo += __shfl_xor_sync(0xffffffffu, slo, 1);
        slo += __shfl_xor_sync(0xffffffffu, slo, 2);
        shi += __shfl_xor_sync(0xffffffffu, shi, 1);
        shi += __shfl_xor_sync(0xffffffffu, shi, 2);
        if (rid == 0) {
            psum[ch * 64 + rlo] = slo;
            psum[ch * 64 + rhi] = shi;
        }
        __syncthreads();

        if (ch == 0 && rid == 0) {
            row_l[rlo] = al_lo * row_l[rlo] + psum[rlo] + psum[64 + rlo];
            row_l[rhi] = al_hi * row_l[rhi] + psum[rhi] + psum[64 + rhi];
            row_m[rlo] = mn_lo;
            row_m[rhi] = mn_hi;
        }

        // --- rescale O, accumulate P @ V (this warp: d-half ch*64) ---
#pragma unroll
        for (int nt = 0; nt < 8; nt++) {
            o[nt][0] *= al_lo; o[nt][1] *= al_lo;
            o[nt][2] *= al_hi; o[nt][3] *= al_hi;
        }
#pragma unroll
        for (int ks = 0; ks < 8; ks++) {
            const int kj = ks * 8;
            uint32_t afr[4];
            afr[0] = f2tf32(Ps[rlo * PP + kj + rid    ]);
            afr[1] = f2tf32(Ps[rhi * PP + kj + rid    ]);
            afr[2] = f2tf32(Ps[rlo * PP + kj + rid + 4]);
            afr[3] = f2tf32(Ps[rhi * PP + kj + rid + 4]);
            uint32_t bfr[8][2];
#pragma unroll
            for (int nt = 0; nt < 8; nt++) {
                const int n = ch * 64 + nt * 8 + qid;
                bfr[nt][0] = f2tf32(Vst[(kj + rid    ) * QP + n]);
                bfr[nt][1] = f2tf32(Vst[(kj + rid + 4) * QP + n]);
            }
#pragma unroll
            for (int nt = 0; nt < 8; nt++)
                mma_tf32(o[nt], afr, bfr[nt]);
        }
        // next iteration's leading __syncthreads separates PV reads (Ps/Vs)
        // from the next chunk's writes.
    }
    __syncthreads();   // row_l final values visible

    // --- epilogue: normalize & scatter to linear ctx layout ---
    float* cb = ctx + bbase;
    const float inv_lo = 1.0f / row_l[rlo];
    const float inv_hi = 1.0f / row_l[rhi];
    const int orow_lo = 2 * (g0 + rlo) + (h >> 3);
    const int orow_hi = 2 * (g0 + rhi) + (h >> 3);
#pragma unroll
    for (int nt = 0; nt < 8; nt++) {
        const int d = ch * 64 + nt * 8 + rid * 2;
        const int ocol = (h & 7) * 128 + d;
        *(float2*)(cb + (size_t)orow_lo * HID + ocol) =
            make_float2(o[nt][0] * inv_lo, o[nt][1] * inv_lo);
        *(float2*)(cb + (size_t)orow_hi * HID + ocol) =
            make_float2(o[nt][2] * inv_hi, o[nt][3] * inv_hi);
    }
}

// ---------------------------------------------------------------------------
extern "C" void kernel_launch(void* const* d_in, const int* in_sizes, int n_in,
                              void* d_out, int out_size)
{
    const float* x  = (const float*)d_in[0];
    const float* Wq = (const float*)d_in[1];
    const float* bq = (const float*)d_in[2];
    const float* Wk = (const float*)d_in[3];
    const float* bk = (const float*)d_in[4];
    const float* Wv = (const float*)d_in[5];
    const float* bv = (const float*)d_in[6];
    const float* Wo = (const float*)d_in[7];
    const float* bo = (const float*)d_in[8];
    float* out = (float*)d_out;

    float *q, *k, *v, *ctx;
    cudaGetSymbolAddress((void**)&q,   g_q);
    cudaGetSymbolAddress((void**)&k,   g_k);
    cudaGetSymbolAddress((void**)&v,   g_v);
    cudaGetSymbolAddress((void**)&ctx, g_ctx);

    cudaFuncSetAttribute(gemm_tf32_nt_bias,
                         cudaFuncAttributeMaxDynamicSharedMemorySize, GEMM_SMEM);

    const dim3 gemm_grid(HID / 128, M_TOT / 128);   // (8, 64)
    gemm_tf32_nt_bias<<<gemm_grid, 256, GEMM_SMEM>>>(x, Wq, bq, q);
    gemm_tf32_nt_bias<<<gemm_grid, 256, GEMM_SMEM>>>(x, Wk, bk, k);
    gemm_tf32_nt_bias<<<gemm_grid, 256, GEMM_SMEM>>>(x, Wv, bv, v);

    cudaFuncSetAttribute(attn_kernel,
                         cudaFuncAttributeMaxDynamicSharedMemorySize, ATTN_SMEM);
    attn_kernel<<<dim3(NG / 64, NH, BATCH), 256, ATTN_SMEM>>>(q, k, v, ctx);

    gemm_tf32_nt_bias<<<gemm_grid, 256, GEMM_SMEM>>>(ctx, Wo, bo, out);
}

// round 7
// speedup vs baseline: 3.4537x; 1.1313x over previous
#include <cuda_runtime.h>
#include <stdint.h>

// Problem dims (compile-time)
#define HID   1024
#define SEQ   2048
#define BATCH 4
#define NH    16
#define NG    1024
#define M_TOT (BATCH * SEQ)   // 8192
#define SCALE 0.125f          // 1/sqrt(64)

// Scratch buffers (static device arrays — no allocs)
__device__ float g_q[(size_t)M_TOT * HID];
__device__ float g_k[(size_t)M_TOT * HID];
__device__ float g_v[(size_t)M_TOT * HID];
__device__ float g_ctx[(size_t)M_TOT * HID];
__device__ float g_x[(size_t)M_TOT * HID];     // tf32-rounded input
__device__ float g_wq[(size_t)HID * HID];      // tf32-rounded weights
__device__ float g_wk[(size_t)HID * HID];
__device__ float g_wv[(size_t)HID * HID];
__device__ float g_wo[(size_t)HID * HID];

// ===========================================================================
// helpers
// ===========================================================================
__device__ __forceinline__ uint32_t smem_u32(const void* p) {
    uint32_t a;
    asm("{ .reg .u64 t; cvta.to.shared.u64 t, %1; cvt.u32.u64 %0, t; }"
        : "=r"(a) : "l"(p));
    return a;
}

__device__ __forceinline__ void cp16(uint32_t dst, const void* src) {
    asm volatile("cp.async.cg.shared.global [%0], [%1], 16;\n"
                 :: "r"(dst), "l"(src));
}
#define CP_COMMIT() asm volatile("cp.async.commit_group;\n" ::: "memory")

__device__ __forceinline__ uint32_t f2tf32(float x) {
    uint32_t r;
    asm("cvt.rna.tf32.f32 %0, %1;" : "=r"(r) : "f"(x));
    return r;
}

// mma.sync m16n8k8 tf32: D += A(16x8 row) * B(8x8 col)
__device__ __forceinline__ void mma_tf32(float* c, const uint32_t* a, const uint32_t* b) {
    asm volatile(
        "mma.sync.aligned.m16n8k8.row.col.f32.tf32.tf32.f32 "
        "{%0,%1,%2,%3}, {%4,%5,%6,%7}, {%8,%9}, {%0,%1,%2,%3};\n"
        : "+f"(c[0]), "+f"(c[1]), "+f"(c[2]), "+f"(c[3])
        : "r"(a[0]), "r"(a[1]), "r"(a[2]), "r"(a[3]), "r"(b[0]), "r"(b[1]));
}

// ===========================================================================
// pre-pass: round fp32 tensor to tf32 (rna), stored as fp32 bits
// ===========================================================================
__global__ __launch_bounds__(256) void round_tf32_kernel(
    const float* __restrict__ in, float* __restrict__ out, int n4)
{
    const int i = blockIdx.x * 256 + threadIdx.x;
    if (i < n4) {
        float4 v = ((const float4*)in)[i];
        float4 r;
        r.x = __uint_as_float(f2tf32(v.x));
        r.y = __uint_as_float(f2tf32(v.y));
        r.z = __uint_as_float(f2tf32(v.z));
        r.w = __uint_as_float(f2tf32(v.w));
        ((float4*)out)[i] = r;
    }
}

// ===========================================================================
// tf32 mma.sync GEMM (NT): C[m,n] = sum_k A[m,k] * W[n,k] + bias[n]
// A and W are PRE-ROUNDED to tf32 -> fragment loads are pure bit loads.
// round_out: 1 -> store C rounded to tf32 (feeds another tf32 GEMM/attention)
// ===========================================================================
#define KC        32
#define NCHUNK    (HID / KC)             // 32
#define GPITCH    36
#define OP_FLOATS (128 * GPITCH)
#define STAGE_FLOATS (2 * OP_FLOATS)
#define GEMM_SMEM (2 * STAGE_FLOATS * 4) // 73728 B

__global__ __launch_bounds__(256) void gemm_tf32_nt_bias(
    const float* __restrict__ A, const float* __restrict__ W,
    const float* __restrict__ bias, float* __restrict__ C, int round_out)
{
    extern __shared__ __align__(16) float smem[];
    const int tid  = threadIdx.x;
    const int wid  = tid >> 5;
    const int lane = tid & 31;
    const int bn   = blockIdx.x;
    const int bm   = blockIdx.y;

    const int wy = wid >> 1;
    const int wx = wid & 1;
    const int qid = lane >> 2;
    const int rid = lane & 3;

    const uint32_t sbase = smem_u32(smem);
    const float* Ab = A + (size_t)bm * 128 * HID;
    const float* Wb = W + (size_t)bn * 128 * HID;

    auto load_chunk = [&](int c, int s) {
        const uint32_t sa = sbase + (uint32_t)(s * STAGE_FLOATS) * 4u;
        const uint32_t sb = sa + (uint32_t)OP_FLOATS * 4u;
        const int k0 = c * KC;
#pragma unroll
        for (int p = 0; p < 4; p++) {
            const int idx = tid + p * 256;
            const int r  = idx >> 3;
            const int cc = idx & 7;
            const uint32_t off = (uint32_t)(r * GPITCH + cc * 4) * 4u;
            const size_t gsrc = (size_t)r * HID + k0 + cc * 4;
            cp16(sa + off, Ab + gsrc);
            cp16(sb + off, Wb + gsrc);
        }
        CP_COMMIT();
    };

    float cacc[2][8][4];
#pragma unroll
    for (int mt = 0; mt < 2; mt++)
#pragma unroll
        for (int nt = 0; nt < 8; nt++)
#pragma unroll
            for (int e = 0; e < 4; e++) cacc[mt][nt][e] = 0.0f;

    load_chunk(0, 0);
    int s = 0;

    for (int c = 0; c < NCHUNK; c++) {
        if (c + 1 < NCHUNK) {
            load_chunk(c + 1, s ^ 1);
            asm volatile("cp.async.wait_group 1;\n" ::: "memory");
        } else {
            asm volatile("cp.async.wait_group 0;\n" ::: "memory");
        }
        __syncthreads();

        const float* As = smem + s * STAGE_FLOATS;
        const float* Bs = As + OP_FLOATS;

#pragma unroll
        for (int ks = 0; ks < 4; ks++) {
            const int k0 = ks * 8;
            uint32_t afr[2][4];
#pragma unroll
            for (int mt = 0; mt < 2; mt++) {
                const int row = wy * 32 + mt * 16 + qid;
                afr[mt][0] = __float_as_uint(As[(row    ) * GPITCH + k0 + rid    ]);
                afr[mt][1] = __float_as_uint(As[(row + 8) * GPITCH + k0 + rid    ]);
                afr[mt][2] = __float_as_uint(As[(row    ) * GPITCH + k0 + rid + 4]);
                afr[mt][3] = __float_as_uint(As[(row + 8) * GPITCH + k0 + rid + 4]);
            }
            uint32_t bfr[8][2];
#pragma unroll
            for (int nt = 0; nt < 8; nt++) {
                const int n = wx * 64 + nt * 8 + qid;
                bfr[nt][0] = __float_as_uint(Bs[n * GPITCH + k0 + rid    ]);
                bfr[nt][1] = __float_as_uint(Bs[n * GPITCH + k0 + rid + 4]);
            }
#pragma unroll
            for (int mt = 0; mt < 2; mt++)
#pragma unroll
                for (int nt = 0; nt < 8; nt++)
                    mma_tf32(cacc[mt][nt], afr[mt], bfr[nt]);
        }
        __syncthreads();
        s ^= 1;
    }

#pragma unroll
    for (int mt = 0; mt < 2; mt++) {
        const int row0 = bm * 128 + wy * 32 + mt * 16 + qid;
#pragma unroll
        for (int nt = 0; nt < 8; nt++) {
            const int col = bn * 128 + wx * 64 + nt * 8 + rid * 2;
            const float b0 = bias[col];
            const float b1 = bias[col + 1];
            float2 r0, r1;
            r0.x = cacc[mt][nt][0] + b0; r0.y = cacc[mt][nt][1] + b1;
            r1.x = cacc[mt][nt][2] + b0; r1.y = cacc[mt][nt][3] + b1;
            if (round_out) {
                r0.x = __uint_as_float(f2tf32(r0.x));
                r0.y = __uint_as_float(f2tf32(r0.y));
                r1.x = __uint_as_float(f2tf32(r1.x));
                r1.y = __uint_as_float(f2tf32(r1.y));
            }
            *(float2*)(C + (size_t)row0 * HID + col)       = r0;
            *(float2*)(C + (size_t)(row0 + 8) * HID + col) = r1;
        }
    }
}

// ===========================================================================
// Tensor-core flash attention over groups. q/k/v are PRE-ROUNDED tf32 ->
// all fragment loads are bit loads. P rounded once at smem store.
// ctx stored tf32-rounded (feeds the out-projection GEMM).
// ===========================================================================
#define QP 132   // pitch for Qs/Ks/Vs rows of 128 floats
#define PP 68    // pitch for Ps (64 cols)

#define SM_QS   0
#define SM_KS   (SM_QS + 64 * QP)            // 2 stages
#define SM_VS   (SM_KS + 2 * 64 * QP)        // 2 stages
#define SM_PS   (SM_VS + 2 * 64 * QP)
#define SM_RM   (SM_PS + 64 * PP)
#define SM_RL   (SM_RM + 64)
#define SM_PM   (SM_RL + 64)                 // [2][64]
#define SM_PSUM (SM_PM + 128)                // [2][64]
#define ATTN_FLOATS (SM_PSUM + 128)
#define ATTN_SMEM (ATTN_FLOATS * 4)

__global__ __launch_bounds__(256) void attn_kernel(
    const float* __restrict__ qlin, const float* __restrict__ klin,
    const float* __restrict__ vlin, float* __restrict__ ctx)
{
    extern __shared__ __align__(16) float sm[];
    float* Qs = sm + SM_QS;
    float* Ks = sm + SM_KS;
    float* Vs = sm + SM_VS;
    float* Ps = sm + SM_PS;
    float* row_m = sm + SM_RM;
    float* row_l = sm + SM_RL;
    float* pmax  = sm + SM_PM;
    float* psum  = sm + SM_PSUM;

    const int tid  = threadIdx.x;
    const int wid  = tid >> 5;
    const int lane = tid & 31;
    const int qid  = lane >> 2;
    const int rid  = lane & 3;
    const int r0   = 16 * (wid & 3);
    const int ch   = wid >> 2;
    const int rlo  = r0 + qid;
    const int rhi  = rlo + 8;

    const int gt = blockIdx.x;
    const int h  = blockIdx.y;
    const int b  = blockIdx.z;
    const int g0 = gt * 64;
    const size_t bbase = (size_t)b * SEQ * HID;
    const float* qb = qlin + bbase;
    const float* kb = klin + bbase;
    const float* vb = vlin + bbase;
    const int hcol = h * 64;

    const uint32_t sbase = smem_u32(sm);
    const uint32_t qs_a = sbase + SM_QS * 4u;

#pragma unroll
    for (int p = 0; p < 8; p++) {
        const int idx = tid + p * 256;
        const int i   = idx >> 5;
        const int d4  = (idx & 31) * 4;
        const int par = d4 >> 6;
        const int cc  = d4 & 63;
        cp16(qs_a + (uint32_t)(i * QP + d4) * 4u,
             qb + (size_t)(2 * (g0 + i) + par) * HID + hcol + cc);
    }
    CP_COMMIT();

    auto loadKV = [&](int c, int s) {
        const uint32_t ka = sbase + (SM_KS + s * 64 * QP) * 4u;
        const uint32_t va = sbase + (SM_VS + s * 64 * QP) * 4u;
        const int j0 = c * 64;
#pragma unroll
        for (int p = 0; p < 8; p++) {
            const int idx = tid + p * 256;
            const int j   = idx >> 5;
            const int d4  = (idx & 31) * 4;
            const int par = d4 >> 6;
            const int cc  = d4 & 63;
            const size_t gs = (size_t)(2 * (j0 + j) + par) * HID + hcol + cc;
            const uint32_t off = (uint32_t)(j * QP + d4) * 4u;
            cp16(ka + off, kb + gs);
            cp16(va + off, vb + gs);
        }
        CP_COMMIT();
    };

    loadKV(0, 0);

    if (tid < 64) { row_m[tid] = -1e30f; row_l[tid] = 0.0f; }

    float o[8][4];
#pragma unroll
    for (int nt = 0; nt < 8; nt++)
#pragma unroll
        for (int e = 0; e < 4; e++) o[nt][e] = 0.0f;

    for (int c = 0; c < 16; c++) {
        const int s = c & 1;
        if (c + 1 < 16) {
            loadKV(c + 1, s ^ 1);
            asm volatile("cp.async.wait_group 1;\n" ::: "memory");
        } else {
            asm volatile("cp.async.wait_group 0;\n" ::: "memory");
        }
        __syncthreads();

        const float* Kst = Ks + s * 64 * QP;
        const float* Vst = Vs + s * 64 * QP;

        // --- S = Q * K^T ---
        float sacc[4][4];
#pragma unroll
        for (int nt = 0; nt < 4; nt++)
#pragma unroll
            for (int e = 0; e < 4; e++) sacc[nt][e] = 0.0f;

#pragma unroll
        for (int ks = 0; ks < 16; ks++) {
            const int k0 = ks * 8;
            uint32_t afr[4];
            afr[0] = __float_as_uint(Qs[rlo * QP + k0 + rid    ]);
            afr[1] = __float_as_uint(Qs[rhi * QP + k0 + rid    ]);
            afr[2] = __float_as_uint(Qs[rlo * QP + k0 + rid + 4]);
            afr[3] = __float_as_uint(Qs[rhi * QP + k0 + rid + 4]);
            uint32_t bfr[4][2];
#pragma unroll
            for (int nt = 0; nt < 4; nt++) {
                const int n = ch * 32 + nt * 8 + qid;
                bfr[nt][0] = __float_as_uint(Kst[n * QP + k0 + rid    ]);
                bfr[nt][1] = __float_as_uint(Kst[n * QP + k0 + rid + 4]);
            }
#pragma unroll
            for (int nt = 0; nt < 4; nt++)
                mma_tf32(sacc[nt], afr, bfr[nt]);
        }
#pragma unroll
        for (int nt = 0; nt < 4; nt++)
#pragma unroll
            for (int e = 0; e < 4; e++) sacc[nt][e] *= SCALE;

        // --- register softmax ---
        float mlo = -1e30f, mhi = -1e30f;
#pragma unroll
        for (int nt = 0; nt < 4; nt++) {
            mlo = fmaxf(mlo, fmaxf(sacc[nt][0], sacc[nt][1]));
            mhi = fmaxf(mhi, fmaxf(sacc[nt][2], sacc[nt][3]));
        }
        mlo = fmaxf(mlo, __shfl_xor_sync(0xffffffffu, mlo, 1));
        mlo = fmaxf(mlo, __shfl_xor_sync(0xffffffffu, mlo, 2));
        mhi = fmaxf(mhi, __shfl_xor_sync(0xffffffffu, mhi, 1));
        mhi = fmaxf(mhi, __shfl_xor_sync(0xffffffffu, mhi, 2));
        if (rid == 0) {
            pmax[ch * 64 + rlo] = mlo;
            pmax[ch * 64 + rhi] = mhi;
        }
        __syncthreads();

        const float mo_lo = row_m[rlo];
        const float mo_hi = row_m[rhi];
        const float mn_lo = fmaxf(mo_lo, fmaxf(pmax[rlo], pmax[64 + rlo]));
        const float mn_hi = fmaxf(mo_hi, fmaxf(pmax[rhi], pmax[64 + rhi]));
        const float al_lo = __expf(mo_lo - mn_lo);
        const float al_hi = __expf(mo_hi - mn_hi);

        float slo = 0.0f, shi = 0.0f;
#pragma unroll
        for (int nt = 0; nt < 4; nt++) {
            float p0 = __expf(sacc[nt][0] - mn_lo);
            float p1 = __expf(sacc[nt][1] - mn_lo);
            float p2 = __expf(sacc[nt][2] - mn_hi);
            float p3 = __expf(sacc[nt][3] - mn_hi);
            slo += p0 + p1;
            shi += p2 + p3;
            const int col = ch * 32 + nt * 8 + rid * 2;
            *(float2*)&Ps[rlo * PP + col] =
                make_float2(__uint_as_float(f2tf32(p0)), __uint_as_float(f2tf32(p1)));
            *(float2*)&Ps[rhi * PP + col] =
                make_float2(__uint_as_float(f2tf32(p2)), __uint_as_float(f2tf32(p3)));
        }
        slo += __shfl_xor_sync(0xffffffffu, slo, 1);
        slo += __shfl_xor_sync(0xffffffffu, slo, 2);
        shi += __shfl_xor_sync(0xffffffffu, shi, 1);
        shi += __shfl_xor_sync(0xffffffffu, shi, 2);
        if (rid == 0) {
            psum[ch * 64 + rlo] = slo;
            psum[ch * 64 + rhi] = shi;
        }
        __syncthreads();

        if (ch == 0 && rid == 0) {
            row_l[rlo] = al_lo * row_l[rlo] + psum[rlo] + psum[64 + rlo];
            row_l[rhi] = al_hi * row_l[rhi] + psum[rhi] + psum[64 + rhi];
            row_m[rlo] = mn_lo;
            row_m[rhi] = mn_hi;
        }

        // --- rescale O, accumulate P @ V ---
#pragma unroll
        for (int nt = 0; nt < 8; nt++) {
            o[nt][0] *= al_lo; o[nt][1] *= al_lo;
            o[nt][2] *= al_hi; o[nt][3] *= al_hi;
        }
#pragma unroll
        for (int ks = 0; ks < 8; ks++) {
            const int kj = ks * 8;
            uint32_t afr[4];
            afr[0] = __float_as_uint(Ps[rlo * PP + kj + rid    ]);
            afr[1] = __float_as_uint(Ps[rhi * PP + kj + rid    ]);
            afr[2] = __float_as_uint(Ps[rlo * PP + kj + rid + 4]);
            afr[3] = __float_as_uint(Ps[rhi * PP + kj + rid + 4]);
            uint32_t bfr[8][2];
#pragma unroll
            for (int nt = 0; nt < 8; nt++) {
                const int n = ch * 64 + nt * 8 + qid;
                bfr[nt][0] = __float_as_uint(Vst[(kj + rid    ) * QP + n]);
                bfr[nt][1] = __float_as_uint(Vst[(kj + rid + 4) * QP + n]);
            }
#pragma unroll
            for (int nt = 0; nt < 8; nt++)
                mma_tf32(o[nt], afr, bfr[nt]);
        }
    }
    __syncthreads();

    // --- epilogue: normalize, round to tf32, scatter to linear ctx layout ---
    float* cb = ctx + bbase;
    const float inv_lo = 1.0f / row_l[rlo];
    const float inv_hi = 1.0f / row_l[rhi];
    const int orow_lo = 2 * (g0 + rlo) + (h >> 3);
    const int orow_hi = 2 * (g0 + rhi) + (h >> 3);
#pragma unroll
    for (int nt = 0; nt < 8; nt++) {
        const int d = ch * 64 + nt * 8 + rid * 2;
        const int ocol = (h & 7) * 128 + d;
        *(float2*)(cb + (size_t)orow_lo * HID + ocol) = make_float2(
            __uint_as_float(f2tf32(o[nt][0] * inv_lo)),
            __uint_as_float(f2tf32(o[nt][1] * inv_lo)));
        *(float2*)(cb + (size_t)orow_hi * HID + ocol) = make_float2(
            __uint_as_float(f2tf32(o[nt][2] * inv_hi)),
            __uint_as_float(f2tf32(o[nt][3] * inv_hi)));
    }
}

// ---------------------------------------------------------------------------
extern "C" void kernel_launch(void* const* d_in, const int* in_sizes, int n_in,
                              void* d_out, int out_size)
{
    const float* x  = (const float*)d_in[0];
    const float* Wq = (const float*)d_in[1];
    const float* bq = (const float*)d_in[2];
    const float* Wk = (const float*)d_in[3];
    const float* bk = (const float*)d_in[4];
    const float* Wv = (const float*)d_in[5];
    const float* bv = (const float*)d_in[6];
    const float* Wo = (const float*)d_in[7];
    const float* bo = (const float*)d_in[8];
    float* out = (float*)d_out;

    float *q, *k, *v, *ctx, *xr, *wq, *wk, *wv, *wo;
    cudaGetSymbolAddress((void**)&q,   g_q);
    cudaGetSymbolAddress((void**)&k,   g_k);
    cudaGetSymbolAddress((void**)&v,   g_v);
    cudaGetSymbolAddress((void**)&ctx, g_ctx);
    cudaGetSymbolAddress((void**)&xr,  g_x);
    cudaGetSymbolAddress((void**)&wq,  g_wq);
    cudaGetSymbolAddress((void**)&wk,  g_wk);
    cudaGetSymbolAddress((void**)&wv,  g_wv);
    cudaGetSymbolAddress((void**)&wo,  g_wo);

    // pre-round inputs and weights to tf32 (once per launch graph)
    const int nx4 = (M_TOT * HID) / 4;
    const int nw4 = (HID * HID) / 4;
    round_tf32_kernel<<<(nx4 + 255) / 256, 256>>>(x,  xr, nx4);
    round_tf32_kernel<<<(nw4 + 255) / 256, 256>>>(Wq, wq, nw4);
    round_tf32_kernel<<<(nw4 + 255) / 256, 256>>>(Wk, wk, nw4);
    round_tf32_kernel<<<(nw4 + 255) / 256, 256>>>(Wv, wv, nw4);
    round_tf32_kernel<<<(nw4 + 255) / 256, 256>>>(Wo, wo, nw4);

    cudaFuncSetAttribute(gemm_tf32_nt_bias,
                         cudaFuncAttributeMaxDynamicSharedMemorySize, GEMM_SMEM);

    const dim3 gemm_grid(HID / 128, M_TOT / 128);   // (8, 64)
    gemm_tf32_nt_bias<<<gemm_grid, 256, GEMM_SMEM>>>(xr, wq, bq, q, 1);
    gemm_tf32_nt_bias<<<gemm_grid, 256, GEMM_SMEM>>>(xr, wk, bk, k, 1);
    gemm_tf32_nt_bias<<<gemm_grid, 256, GEMM_SMEM>>>(xr, wv, bv, v, 1);

    cudaFuncSetAttribute(attn_kernel,
                         cudaFuncAttributeMaxDynamicSharedMemorySize, ATTN_SMEM);
    attn_kernel<<<dim3(NG / 64, NH, BATCH), 256, ATTN_SMEM>>>(q, k, v, ctx);

    gemm_tf32_nt_bias<<<gemm_grid, 256, GEMM_SMEM>>>(ctx, wo, bo, out, 0);
}

// round 8
// speedup vs baseline: 4.2875x; 1.2414x over previous
#include <cuda_runtime.h>
#include <stdint.h>

// Problem dims (compile-time)
#define HID   1024
#define SEQ   2048
#define BATCH 4
#define NH    16
#define NG    1024
#define M_TOT (BATCH * SEQ)   // 8192
#define SCALE 0.125f          // 1/sqrt(64)

// Scratch buffers (static device arrays — no allocs)
__device__ float g_q[(size_t)M_TOT * HID];
__device__ float g_k[(size_t)M_TOT * HID];
__device__ float g_v[(size_t)M_TOT * HID];
__device__ float g_ctx[(size_t)M_TOT * HID];
__device__ float g_x[(size_t)M_TOT * HID];     // tf32-rounded input
__device__ float g_wq[(size_t)HID * HID];      // tf32-rounded weights
__device__ float g_wk[(size_t)HID * HID];
__device__ float g_wv[(size_t)HID * HID];
__device__ float g_wo[(size_t)HID * HID];

// ===========================================================================
// helpers
// ===========================================================================
__device__ __forceinline__ uint32_t smem_u32(const void* p) {
    uint32_t a;
    asm("{ .reg .u64 t; cvta.to.shared.u64 t, %1; cvt.u32.u64 %0, t; }"
        : "=r"(a) : "l"(p));
    return a;
}

__device__ __forceinline__ void cp16(uint32_t dst, const void* src) {
    asm volatile("cp.async.cg.shared.global [%0], [%1], 16;\n"
                 :: "r"(dst), "l"(src));
}
#define CP_COMMIT() asm volatile("cp.async.commit_group;\n" ::: "memory")
#define CP_WAIT0()  asm volatile("cp.async.wait_group 0;\n" ::: "memory")
#define CP_WAIT1()  asm volatile("cp.async.wait_group 1;\n" ::: "memory")

__device__ __forceinline__ uint32_t f2tf32(float x) {
    uint32_t r;
    asm("cvt.rna.tf32.f32 %0, %1;" : "=r"(r) : "f"(x));
    return r;
}

// mma.sync m16n8k8 tf32: D += A(16x8 row) * B(8x8 col)
__device__ __forceinline__ void mma_tf32(float* c, const uint32_t* a, const uint32_t* b) {
    asm volatile(
        "mma.sync.aligned.m16n8k8.row.col.f32.tf32.tf32.f32 "
        "{%0,%1,%2,%3}, {%4,%5,%6,%7}, {%8,%9}, {%0,%1,%2,%3};\n"
        : "+f"(c[0]), "+f"(c[1]), "+f"(c[2]), "+f"(c[3])
        : "r"(a[0]), "r"(a[1]), "r"(a[2]), "r"(a[3]), "r"(b[0]), "r"(b[1]));
}

// ===========================================================================
// pre-pass: round fp32 tensors to tf32 (rna), stored as fp32 bits
// ===========================================================================
__global__ __launch_bounds__(256) void round_tf32_kernel(
    const float* __restrict__ in, float* __restrict__ out, int n4)
{
    const int i = blockIdx.x * 256 + threadIdx.x;
    if (i < n4) {
        float4 v = ((const float4*)in)[i];
        float4 r;
        r.x = __uint_as_float(f2tf32(v.x));
        r.y = __uint_as_float(f2tf32(v.y));
        r.z = __uint_as_float(f2tf32(v.z));
        r.w = __uint_as_float(f2tf32(v.w));
        ((float4*)out)[i] = r;
    }
}

__global__ __launch_bounds__(256) void round_w_kernel(
    const float* __restrict__ w0, const float* __restrict__ w1,
    const float* __restrict__ w2, const float* __restrict__ w3,
    float* __restrict__ o0, float* __restrict__ o1,
    float* __restrict__ o2, float* __restrict__ o3, int n4)
{
    const int z = blockIdx.y;
    const float* in = z == 0 ? w0 : (z == 1 ? w1 : (z == 2 ? w2 : w3));
    float* out      = z == 0 ? o0 : (z == 1 ? o1 : (z == 2 ? o2 : o3));
    const int i = blockIdx.x * 256 + threadIdx.x;
    if (i < n4) {
        float4 v = ((const float4*)in)[i];
        float4 r;
        r.x = __uint_as_float(f2tf32(v.x));
        r.y = __uint_as_float(f2tf32(v.y));
        r.z = __uint_as_float(f2tf32(v.z));
        r.w = __uint_as_float(f2tf32(v.w));
        ((float4*)out)[i] = r;
    }
}

// ===========================================================================
// tf32 mma.sync GEMM (NT), 3-stage cp.async pipeline, fused over blockIdx.z:
// C_z[m,n] = sum_k A[m,k] * W_z[n,k] + bias_z[n]. A, W pre-rounded tf32.
// ===========================================================================
#define KC        32
#define NCHUNK    (HID / KC)             // 32
#define GPITCH    36
#define OP_FLOATS (128 * GPITCH)
#define STAGE_FLOATS (2 * OP_FLOATS)     // 9216 floats
#define GEMM_SMEM (3 * STAGE_FLOATS * 4) // 110592 B

__global__ __launch_bounds__(256) void gemm_tf32_3(
    const float* __restrict__ A,
    const float* __restrict__ W0, const float* __restrict__ W1,
    const float* __restrict__ W2,
    const float* __restrict__ b0, const float* __restrict__ b1,
    const float* __restrict__ b2,
    float* __restrict__ C0, float* __restrict__ C1, float* __restrict__ C2,
    int round_out)
{
    extern __shared__ __align__(16) float smem[];
    const int tid  = threadIdx.x;
    const int wid  = tid >> 5;
    const int lane = tid & 31;
    const int bn   = blockIdx.x;
    const int bm   = blockIdx.y;
    const int z    = blockIdx.z;

    const float* W    = z == 0 ? W0 : (z == 1 ? W1 : W2);
    const float* bias = z == 0 ? b0 : (z == 1 ? b1 : b2);
    float* C          = z == 0 ? C0 : (z == 1 ? C1 : C2);

    const int wy = wid >> 1;
    const int wx = wid & 1;
    const int qid = lane >> 2;
    const int rid = lane & 3;

    const uint32_t sbase = smem_u32(smem);
    const float* Ab = A + (size_t)bm * 128 * HID;
    const float* Wb = W + (size_t)bn * 128 * HID;

    auto load_chunk = [&](int c, int s) {
        const uint32_t sa = sbase + (uint32_t)(s * STAGE_FLOATS) * 4u;
        const uint32_t sb = sa + (uint32_t)OP_FLOATS * 4u;
        const int k0 = c * KC;
#pragma unroll
        for (int p = 0; p < 4; p++) {
            const int idx = tid + p * 256;
            const int r  = idx >> 3;
            const int cc = idx & 7;
            const uint32_t off = (uint32_t)(r * GPITCH + cc * 4) * 4u;
            const size_t gsrc = (size_t)r * HID + k0 + cc * 4;
            cp16(sa + off, Ab + gsrc);
            cp16(sb + off, Wb + gsrc);
        }
        CP_COMMIT();
    };

    float cacc[2][8][4];
#pragma unroll
    for (int mt = 0; mt < 2; mt++)
#pragma unroll
        for (int nt = 0; nt < 8; nt++)
#pragma unroll
            for (int e = 0; e < 4; e++) cacc[mt][nt][e] = 0.0f;

    load_chunk(0, 0);
    load_chunk(1, 1);

    for (int c = 0; c < NCHUNK; c++) {
        if (c == NCHUNK - 1) { CP_WAIT0(); } else { CP_WAIT1(); }
        __syncthreads();
        if (c + 2 < NCHUNK) load_chunk(c + 2, (c + 2) % 3);

        const float* As = smem + (c % 3) * STAGE_FLOATS;
        const float* Bs = As + OP_FLOATS;

#pragma unroll
        for (int ks = 0; ks < 4; ks++) {
            const int k0 = ks * 8;
            uint32_t afr[2][4];
#pragma unroll
            for (int mt = 0; mt < 2; mt++) {
                const int row = wy * 32 + mt * 16 + qid;
                afr[mt][0] = __float_as_uint(As[(row    ) * GPITCH + k0 + rid    ]);
                afr[mt][1] = __float_as_uint(As[(row + 8) * GPITCH + k0 + rid    ]);
                afr[mt][2] = __float_as_uint(As[(row    ) * GPITCH + k0 + rid + 4]);
                afr[mt][3] = __float_as_uint(As[(row + 8) * GPITCH + k0 + rid + 4]);
            }
            uint32_t bfr[8][2];
#pragma unroll
            for (int nt = 0; nt < 8; nt++) {
                const int n = wx * 64 + nt * 8 + qid;
                bfr[nt][0] = __float_as_uint(Bs[n * GPITCH + k0 + rid    ]);
                bfr[nt][1] = __float_as_uint(Bs[n * GPITCH + k0 + rid + 4]);
            }
#pragma unroll
            for (int mt = 0; mt < 2; mt++)
#pragma unroll
                for (int nt = 0; nt < 8; nt++)
                    mma_tf32(cacc[mt][nt], afr[mt], bfr[nt]);
        }
        // no trailing sync needed: stage (c%3) is only overwritten by the
        // load issued at iteration c+1, which is after its leading barrier.
    }

#pragma unroll
    for (int mt = 0; mt < 2; mt++) {
        const int row0 = bm * 128 + wy * 32 + mt * 16 + qid;
#pragma unroll
        for (int nt = 0; nt < 8; nt++) {
            const int col = bn * 128 + wx * 64 + nt * 8 + rid * 2;
            const float b0v = bias[col];
            const float b1v = bias[col + 1];
            float2 r0, r1;
            r0.x = cacc[mt][nt][0] + b0v; r0.y = cacc[mt][nt][1] + b1v;
            r1.x = cacc[mt][nt][2] + b0v; r1.y = cacc[mt][nt][3] + b1v;
            if (round_out) {
                r0.x = __uint_as_float(f2tf32(r0.x));
                r0.y = __uint_as_float(f2tf32(r0.y));
                r1.x = __uint_as_float(f2tf32(r1.x));
                r1.y = __uint_as_float(f2tf32(r1.y));
            }
            *(float2*)(C + (size_t)row0 * HID + col)       = r0;
            *(float2*)(C + (size_t)(row0 + 8) * HID + col) = r1;
        }
    }
}

// ===========================================================================
// Tensor-core flash attention v2: q-tile 128, warp-local softmax.
// Block = (qt, h, b): 256 threads / 8 warps; warp w owns rows 16w..16w+15
// of the q-tile for BOTH S (full 64-col chunk width) and PV (full d=128).
// Q fragments hoisted into registers once. Row m/l state in registers.
// One __syncthreads per chunk; P is warp-private smem (__syncwarp only).
// ===========================================================================
#define KP 132   // K / Q-stage pitch
#define VP 136   // V pitch (conflict-free for (k-row, d-col) access)
#define PP 68    // P pitch

#define SM_KS   0                        // 2 stages: 2*64*KP  (Q staged here)
#define SM_VS   (2 * 64 * KP)            // 2 stages: 2*64*VP
#define SM_PS   (SM_VS + 2 * 64 * VP)    // 128*PP
#define ATTN_FLOATS (SM_PS + 128 * PP)   // 43008 floats
#define ATTN_SMEM   (ATTN_FLOATS * 4)    // 172032 B

__global__ __launch_bounds__(256) void attn_kernel(
    const float* __restrict__ qlin, const float* __restrict__ klin,
    const float* __restrict__ vlin, float* __restrict__ ctx)
{
    extern __shared__ __align__(16) float sm[];
    float* Ks = sm + SM_KS;
    float* Vs = sm + SM_VS;
    float* Ps = sm + SM_PS;

    const int tid  = threadIdx.x;
    const int wid  = tid >> 5;
    const int lane = tid & 31;
    const int qid  = lane >> 2;
    const int rid  = lane & 3;
    const int rlo  = 16 * wid + qid;
    const int rhi  = rlo + 8;

    const int gt = blockIdx.x;          // 0..7, q-tile of 128 groups
    const int h  = blockIdx.y;
    const int b  = blockIdx.z;
    const int g0 = gt * 128;
    const size_t bbase = (size_t)b * SEQ * HID;
    const float* qb = qlin + bbase;
    const float* kb = klin + bbase;
    const float* vb = vlin + bbase;
    const int hcol = h * 64;

    const uint32_t sbase = smem_u32(sm);

    // --- stage Q (128 rows x 128 floats) into Ks region, pitch KP ---
#pragma unroll
    for (int p = 0; p < 16; p++) {
        const int idx = tid + p * 256;
        const int i   = idx >> 5;
        const int d4  = (idx & 31) * 4;
        const int par = d4 >> 6;
        const int cc  = d4 & 63;
        cp16(sbase + (uint32_t)(i * KP + d4) * 4u,
             qb + (size_t)(2 * (g0 + i) + par) * HID + hcol + cc);
    }
    CP_COMMIT();
    CP_WAIT0();
    __syncthreads();

    // --- extract Q fragments to registers (reused for all chunks) ---
    uint32_t qfr[16][4];
#pragma unroll
    for (int ks = 0; ks < 16; ks++) {
        const int k0 = ks * 8;
        qfr[ks][0] = __float_as_uint(Ks[rlo * KP + k0 + rid    ]);
        qfr[ks][1] = __float_as_uint(Ks[rhi * KP + k0 + rid    ]);
        qfr[ks][2] = __float_as_uint(Ks[rlo * KP + k0 + rid + 4]);
        qfr[ks][3] = __float_as_uint(Ks[rhi * KP + k0 + rid + 4]);
    }
    __syncthreads();   // all warps done reading Q stage before K overwrites

    auto loadKV = [&](int c, int s) {
        const uint32_t ka = sbase + (uint32_t)(SM_KS + s * 64 * KP) * 4u;
        const uint32_t va = sbase + (uint32_t)(SM_VS + s * 64 * VP) * 4u;
        const int j0 = c * 64;
#pragma unroll
        for (int p = 0; p < 8; p++) {
            const int idx = tid + p * 256;
            const int j   = idx >> 5;
            const int d4  = (idx & 31) * 4;
            const int par = d4 >> 6;
            const int cc  = d4 & 63;
            const size_t gs = (size_t)(2 * (j0 + j) + par) * HID + hcol + cc;
            cp16(ka + (uint32_t)(j * KP + d4) * 4u, kb + gs);
            cp16(va + (uint32_t)(j * VP + d4) * 4u, vb + gs);
        }
        CP_COMMIT();
    };

    loadKV(0, 0);

    float m_lo = -1e30f, m_hi = -1e30f, l_lo = 0.0f, l_hi = 0.0f;
    float o[16][4];
#pragma unroll
    for (int nt = 0; nt < 16; nt++)
#pragma unroll
        for (int e = 0; e < 4; e++) o[nt][e] = 0.0f;

    for (int c = 0; c < 16; c++) {
        const int s = c & 1;
        CP_WAIT0();
        __syncthreads();               // chunk c resident; all warps past c-1
        if (c + 1 < 16) loadKV(c + 1, s ^ 1);

        const float* Kst = Ks + s * 64 * KP;
        const float* Vst = Vs + s * 64 * VP;

        // --- S = Q K^T: this warp rows 16w..+15, full 64 chunk cols ---
        float sacc[8][4];
#pragma unroll
        for (int nt = 0; nt < 8; nt++)
#pragma unroll
            for (int e = 0; e < 4; e++) sacc[nt][e] = 0.0f;

#pragma unroll
        for (int ks = 0; ks < 16; ks++) {
            const int k0 = ks * 8;
            uint32_t bfr[8][2];
#pragma unroll
            for (int nt = 0; nt < 8; nt++) {
                const int n = nt * 8 + qid;
                bfr[nt][0] = __float_as_uint(Kst[n * KP + k0 + rid    ]);
                bfr[nt][1] = __float_as_uint(Kst[n * KP + k0 + rid + 4]);
            }
#pragma unroll
            for (int nt = 0; nt < 8; nt++)
                mma_tf32(sacc[nt], qfr[ks], bfr[nt]);
        }

        // --- warp-local online softmax (rows rlo, rhi) ---
        float vlo = -1e30f, vhi = -1e30f;
#pragma unroll
        for (int nt = 0; nt < 8; nt++) {
            sacc[nt][0] *= SCALE; sacc[nt][1] *= SCALE;
            sacc[nt][2] *= SCALE; sacc[nt][3] *= SCALE;
            vlo = fmaxf(vlo, fmaxf(sacc[nt][0], sacc[nt][1]));
            vhi = fmaxf(vhi, fmaxf(sacc[nt][2], sacc[nt][3]));
        }
        vlo = fmaxf(vlo, __shfl_xor_sync(0xffffffffu, vlo, 1));
        vlo = fmaxf(vlo, __shfl_xor_sync(0xffffffffu, vlo, 2));
        vhi = fmaxf(vhi, __shfl_xor_sync(0xffffffffu, vhi, 1));
        vhi = fmaxf(vhi, __shfl_xor_sync(0xffffffffu, vhi, 2));

        const float mn_lo = fmaxf(m_lo, vlo);
        const float mn_hi = fmaxf(m_hi, vhi);
        const float al_lo = __expf(m_lo - mn_lo);
        const float al_hi = __expf(m_hi - mn_hi);
        m_lo = mn_lo; m_hi = mn_hi;

        float slo = 0.0f, shi = 0.0f;
#pragma unroll
        for (int nt = 0; nt < 8; nt++) {
            float p0 = __expf(sacc[nt][0] - mn_lo);
            float p1 = __expf(sacc[nt][1] - mn_lo);
            float p2 = __expf(sacc[nt][2] - mn_hi);
            float p3 = __expf(sacc[nt][3] - mn_hi);
            slo += p0 + p1;
            shi += p2 + p3;
            const int col = nt * 8 + rid * 2;
            *(float2*)&Ps[rlo * PP + col] =
                make_float2(__uint_as_float(f2tf32(p0)), __uint_as_float(f2tf32(p1)));
            *(float2*)&Ps[rhi * PP + col] =
                make_float2(__uint_as_float(f2tf32(p2)), __uint_as_float(f2tf32(p3)));
        }
        slo += __shfl_xor_sync(0xffffffffu, slo, 1);
        slo += __shfl_xor_sync(0xffffffffu, slo, 2);
        shi += __shfl_xor_sync(0xffffffffu, shi, 1);
        shi += __shfl_xor_sync(0xffffffffu, shi, 2);
        l_lo = l_lo * al_lo + slo;
        l_hi = l_hi * al_hi + shi;

        __syncwarp();   // P rows of this warp written before PV reads them

        // --- rescale O, accumulate P @ V (rows rlo/rhi, full d=128) ---
#pragma unroll
        for (int nt = 0; nt < 16; nt++) {
            o[nt][0] *= al_lo; o[nt][1] *= al_lo;
            o[nt][2] *= al_hi; o[nt][3] *= al_hi;
        }
#pragma unroll
        for (int ks = 0; ks < 8; ks++) {
            const int kj = ks * 8;
            uint32_t afr[4];
            afr[0] = __float_as_uint(Ps[rlo * PP + kj + rid    ]);
            afr[1] = __float_as_uint(Ps[rhi * PP + kj + rid    ]);
            afr[2] = __float_as_uint(Ps[rlo * PP + kj + rid + 4]);
            afr[3] = __float_as_uint(Ps[rhi * PP + kj + rid + 4]);
            uint32_t bfr[16][2];
#pragma unroll
            for (int nt = 0; nt < 16; nt++) {
                const int n = nt * 8 + qid;
                bfr[nt][0] = __float_as_uint(Vst[(kj + rid    ) * VP + n]);
                bfr[nt][1] = __float_as_uint(Vst[(kj + rid + 4) * VP + n]);
            }
#pragma unroll
            for (int nt = 0; nt < 16; nt++)
                mma_tf32(o[nt], afr, bfr[nt]);
        }
        // stage s is only overwritten by the load issued at iteration c+1,
        // after its leading __syncthreads -> no trailing barrier needed.
    }

    // --- epilogue: normalize, round tf32, scatter to linear ctx layout ---
    float* cb = ctx + bbase;
    const float inv_lo = 1.0f / l_lo;
    const float inv_hi = 1.0f / l_hi;
    const int orow_lo = 2 * (g0 + rlo) + (h >> 3);
    const int orow_hi = 2 * (g0 + rhi) + (h >> 3);
#pragma unroll
    for (int nt = 0; nt < 16; nt++) {
        const int d = nt * 8 + rid * 2;
        const int ocol = (h & 7) * 128 + d;
        *(float2*)(cb + (size_t)orow_lo * HID + ocol) = make_float2(
            __uint_as_float(f2tf32(o[nt][0] * inv_lo)),
            __uint_as_float(f2tf32(o[nt][1] * inv_lo)));
        *(float2*)(cb + (size_t)orow_hi * HID + ocol) = make_float2(
            __uint_as_float(f2tf32(o[nt][2] * inv_hi)),
            __uint_as_float(f2tf32(o[nt][3] * inv_hi)));
    }
}

// ---------------------------------------------------------------------------
extern "C" void kernel_launch(void* const* d_in, const int* in_sizes, int n_in,
                              void* d_out, int out_size)
{
    const float* x  = (const float*)d_in[0];
    const float* Wq = (const float*)d_in[1];
    const float* bq = (const float*)d_in[2];
    const float* Wk = (const float*)d_in[3];
    const float* bk = (const float*)d_in[4];
    const float* Wv = (const float*)d_in[5];
    const float* bv = (const float*)d_in[6];
    const float* Wo = (const float*)d_in[7];
    const float* bo = (const float*)d_in[8];
    float* out = (float*)d_out;

    float *q, *k, *v, *ctx, *xr, *wq, *wk, *wv, *wo;
    cudaGetSymbolAddress((void**)&q,   g_q);
    cudaGetSymbolAddress((void**)&k,   g_k);
    cudaGetSymbolAddress((void**)&v,   g_v);
    cudaGetSymbolAddress((void**)&ctx, g_ctx);
    cudaGetSymbolAddress((void**)&xr,  g_x);
    cudaGetSymbolAddress((void**)&wq,  g_wq);
    cudaGetSymbolAddress((void**)&wk,  g_wk);
    cudaGetSymbolAddress((void**)&wv,  g_wv);
    cudaGetSymbolAddress((void**)&wo,  g_wo);

    // pre-round input and weights to tf32
    const int nx4 = (M_TOT * HID) / 4;
    const int nw4 = (HID * HID) / 4;
    round_tf32_kernel<<<(nx4 + 255) / 256, 256>>>(x, xr, nx4);
    round_w_kernel<<<dim3((nw4 + 255) / 256, 4), 256>>>(
        Wq, Wk, Wv, Wo, wq, wk, wv, wo, nw4);

    cudaFuncSetAttribute(gemm_tf32_3,
                         cudaFuncAttributeMaxDynamicSharedMemorySize, GEMM_SMEM);
    cudaFuncSetAttribute(attn_kernel,
                         cudaFuncAttributeMaxDynamicSharedMemorySize, ATTN_SMEM);

    // fused Q/K/V projection (grid.z picks weight/bias/output)
    gemm_tf32_3<<<dim3(HID / 128, M_TOT / 128, 3), 256, GEMM_SMEM>>>(
        xr, wq, wk, wv, bq, bk, bv, q, k, v, 1);

    attn_kernel<<<dim3(NG / 128, NH, BATCH), 256, ATTN_SMEM>>>(q, k, v, ctx);

    // output projection
    gemm_tf32_3<<<dim3(HID / 128, M_TOT / 128, 1), 256, GEMM_SMEM>>>(
        ctx, wo, wo, wo, bo, bo, bo, out, out, out, 0);
}